// round 8
// baseline (speedup 1.0000x reference)
#include <cuda_runtime.h>
#include <cuda_fp16.h>
#include <math.h>
#include <stdint.h>

// ---------------------------------------------------------------------------
// GCNJointPredictor, round 8 (resubmit of round 7; infra failure last round):
//  - agg1 fused into gemm2 prologue (H1 never hits DRAM; R1 fp16, error-free)
//  - agg2 fused into readout (H2 never materialized; R2 stays fp32)
//  - norm fused into chunksum; MLP 16 rows/block (2x parallelism)
//  - GEMM mainloop unchanged from round 6 (61.8us, smem-bound)
// ---------------------------------------------------------------------------

#define NMAX 100000
#define EMAX 3200000
#define BMAX 4096
#define HD   128
#define BN_INV 0.9999950000374997f
#define SCAN_CHUNK 1024

// ---- scratch (device globals) ----
__device__ __align__(16) __half g_Ph1[(size_t)NMAX * HD];
__device__ __align__(16) __half g_Rh1[(size_t)NMAX * HD];
__device__ __align__(16) __half g_Ph2[(size_t)NMAX * HD];
__device__ __align__(16) float  g_R2f[(size_t)NMAX * HD];
__device__ __align__(16) float  g_Z[(size_t)BMAX * HD];
__device__ __align__(16) float  g_X2[(size_t)BMAX * 832];
__device__ __align__(16) __half g_Wt[2][256 * 128];   // [layer][n][k] fp16 transposed
__device__ int   g_deg_src[NMAX];
__device__ int   g_deg_dst[NMAX];
__device__ float g_out_norm[NMAX];
__device__ float g_in_norm[NMAX];
__device__ int   g_row_ptr[NMAX + 1];
__device__ int   g_cursor[NMAX];
__device__ int   g_esrc[EMAX];
__device__ int   g_bsum[256];
__device__ int   g_boff[256];

// ---------------------------------------------------------------------------
// one-shot weight transpose to fp16: Wt[n][k] = half(W[k][n])
// ---------------------------------------------------------------------------
__global__ void k_wconv(const float* __restrict__ W1, const float* __restrict__ rW1,
                        const float* __restrict__ W2, const float* __restrict__ rW2)
{
    int i = blockIdx.x * blockDim.x + threadIdx.x;
    if (i >= 2 * 256 * 128) return;
    int layer = i >> 15;
    int j = i & 32767;
    int n = j >> 7, k = j & 127;
    const float* src = (layer == 0) ? ((n < 128) ? W1 : rW1)
                                    : ((n < 128) ? W2 : rW2);
    g_Wt[layer][(size_t)n * 128 + k] = __float2half(src[(size_t)k * 128 + (n & 127)]);
}

// ---------------------------------------------------------------------------
// degrees
// ---------------------------------------------------------------------------
__global__ void k_deg(const int* __restrict__ src, const int* __restrict__ dst, int E) {
    int e = blockIdx.x * blockDim.x + threadIdx.x;
    if (e < E) {
        atomicAdd(&g_deg_src[src[e]], 1);
        atomicAdd(&g_deg_dst[dst[e]], 1);
    }
}

// ---------------------------------------------------------------------------
// fused: norms + per-chunk sum of deg_dst (for the scan)
// ---------------------------------------------------------------------------
__global__ void k_normchunk(int Nn) {
    __shared__ int sdata[256];
    int base = blockIdx.x * SCAN_CHUNK;
    int s = 0;
    for (int i = threadIdx.x; i < SCAN_CHUNK; i += 256) {
        int idx = base + i;
        if (idx < Nn) {
            int ds = g_deg_src[idx], dd = g_deg_dst[idx];
            g_out_norm[idx] = rsqrtf((float)max(ds, 1));
            g_in_norm[idx]  = rsqrtf((float)max(dd, 1));
            s += dd;
        }
    }
    sdata[threadIdx.x] = s;
    __syncthreads();
    for (int off = 128; off > 0; off >>= 1) {
        if (threadIdx.x < off) sdata[threadIdx.x] += sdata[threadIdx.x + off];
        __syncthreads();
    }
    if (threadIdx.x == 0) g_bsum[blockIdx.x] = sdata[0];
}

__global__ void k_scan_bsums(int nb, int Nn) {
    __shared__ int s[256];
    int t = threadIdx.x;
    int v = (t < nb) ? g_bsum[t] : 0;
    s[t] = v;
    __syncthreads();
#pragma unroll
    for (int d = 1; d < 256; d <<= 1) {
        int x = (t >= d) ? s[t - d] : 0;
        __syncthreads();
        s[t] += x;
        __syncthreads();
    }
    if (t < nb) g_boff[t] = s[t] - v;
    if (t == 0) g_row_ptr[Nn] = s[255];
}

__global__ void k_scan_final(int Nn) {
    __shared__ int s0[SCAN_CHUNK];
    __shared__ int s1[SCAN_CHUNK];
    int base = blockIdx.x * SCAN_CHUNK;
    for (int i = threadIdx.x; i < SCAN_CHUNK; i += 256) {
        int idx = base + i;
        s0[i] = (idx < Nn) ? g_deg_dst[idx] : 0;
    }
    __syncthreads();
    int* a = s0; int* b = s1;
    for (int d = 1; d < SCAN_CHUNK; d <<= 1) {
        for (int i = threadIdx.x; i < SCAN_CHUNK; i += 256)
            b[i] = a[i] + (i >= d ? a[i - d] : 0);
        __syncthreads();
        int* t = a; a = b; b = t;
    }
    int off = g_boff[blockIdx.x];
    for (int i = threadIdx.x; i < SCAN_CHUNK; i += 256) {
        int idx = base + i;
        if (idx < Nn) {
            int ex = off + (i > 0 ? a[i - 1] : 0);
            g_row_ptr[idx] = ex;
            g_cursor[idx]  = ex;
        }
    }
}

__global__ void k_build(const int* __restrict__ src, const int* __restrict__ dst, int E) {
    int e = blockIdx.x * blockDim.x + threadIdx.x;
    if (e < E) {
        int p = atomicAdd(&g_cursor[dst[e]], 1);
        g_esrc[p] = src[e];
    }
}

// ---------------------------------------------------------------------------
// CSR gather: sum of fp16 P rows over a node's in-edges (4-edge unroll)
// lane handles features [lane*4, lane*4+4)
// ---------------------------------------------------------------------------
__device__ __forceinline__ float4 gather_row(const __half* __restrict__ P,
                                             int e0, int e1, int lane)
{
    const uint2* P2 = reinterpret_cast<const uint2*>(P);
    float4 acc = make_float4(0.f, 0.f, 0.f, 0.f);
    int e = e0;
#define ACCV(v) { \
    float2 p0 = __half22float2(*reinterpret_cast<__half2*>(&(v).x)); \
    float2 p1 = __half22float2(*reinterpret_cast<__half2*>(&(v).y)); \
    acc.x += p0.x; acc.y += p0.y; acc.z += p1.x; acc.w += p1.y; }
    for (; e + 3 < e1; e += 4) {
        int u0 = g_esrc[e],     u1 = g_esrc[e + 1];
        int u2 = g_esrc[e + 2], u3 = g_esrc[e + 3];
        uint2 v0 = P2[(size_t)u0 * 32 + lane];
        uint2 v1 = P2[(size_t)u1 * 32 + lane];
        uint2 v2 = P2[(size_t)u2 * 32 + lane];
        uint2 v3 = P2[(size_t)u3 * 32 + lane];
        ACCV(v0); ACCV(v1); ACCV(v2); ACCV(v3);
    }
    for (; e < e1; e++) {
        int u = g_esrc[e];
        uint2 v = P2[(size_t)u * 32 + lane];
        ACCV(v);
    }
#undef ACCV
    return acc;
}

// ---------------------------------------------------------------------------
// fused fp16 tensor-core GEMM core pieces (shared by l1 / l2 kernels)
// block: 128 rows x 256 cols, 512 thr (16 warps, 4M x 4N), warp tile 32x64
// Smem ~102KB: W[256][136] fp16 + X[128][136] fp16; one barrier.
// Epilogue: cols [0,128) -> P fp16 * rowscale; cols [128,256) -> R relu
//   (R to fp16 RoutH if non-null, else fp32 RoutF)
// ---------------------------------------------------------------------------
#define WP 136
#define GEMM_SMEM ((256 * WP + 128 * WP) * 2)   // 104448 bytes

#define MMA_F16(c, a0, a1, a2, a3, b0, b1)                                   \
    asm volatile(                                                            \
        "mma.sync.aligned.m16n8k16.row.col.f32.f16.f16.f32 "                 \
        "{%0,%1,%2,%3}, {%4,%5,%6,%7}, {%8,%9}, {%0,%1,%2,%3};"              \
        : "+f"((c)[0]), "+f"((c)[1]), "+f"((c)[2]), "+f"((c)[3])             \
        : "r"(a0), "r"(a1), "r"(a2), "r"(a3), "r"(b0), "r"(b1))

#define GEMM_MAIN_AND_EPI()                                                  \
    float acc[2][8][4];                                                      \
    _Pragma("unroll")                                                        \
    for (int mt = 0; mt < 2; mt++)                                           \
        _Pragma("unroll")                                                    \
        for (int nt = 0; nt < 8; nt++)                                       \
            _Pragma("unroll")                                                \
            for (int q = 0; q < 4; q++) acc[mt][nt][q] = 0.f;                \
    _Pragma("unroll")                                                        \
    for (int c = 0; c < 8; c++) {                                            \
        int kk = c * 16;                                                     \
        uint32_t a[2][4];                                                    \
        _Pragma("unroll")                                                    \
        for (int mt = 0; mt < 2; mt++) {                                     \
            int r = wm * 32 + mt * 16 + gq;                                  \
            a[mt][0] = *reinterpret_cast<uint32_t*>(&Xs[r * WP + kk + tg * 2]);          \
            a[mt][1] = *reinterpret_cast<uint32_t*>(&Xs[(r + 8) * WP + kk + tg * 2]);    \
            a[mt][2] = *reinterpret_cast<uint32_t*>(&Xs[r * WP + kk + 8 + tg * 2]);      \
            a[mt][3] = *reinterpret_cast<uint32_t*>(&Xs[(r + 8) * WP + kk + 8 + tg * 2]);\
        }                                                                    \
        _Pragma("unroll")                                                    \
        for (int nt = 0; nt < 8; nt++) {                                     \
            int nb = wn * 64 + nt * 8 + gq;                                  \
            uint32_t b0 = *reinterpret_cast<uint32_t*>(&Ws[nb * WP + kk + tg * 2]);      \
            uint32_t b1 = *reinterpret_cast<uint32_t*>(&Ws[nb * WP + kk + 8 + tg * 2]);  \
            _Pragma("unroll")                                                \
            for (int mt = 0; mt < 2; mt++)                                   \
                MMA_F16(acc[mt][nt], a[mt][0], a[mt][1], a[mt][2], a[mt][3], b0, b1);    \
        }                                                                    \
    }                                                                        \
    _Pragma("unroll")                                                        \
    for (int mt = 0; mt < 2; mt++) {                                         \
        int r0 = row0 + wm * 32 + mt * 16 + gq;                              \
        int r1 = r0 + 8;                                                     \
        if (wn < 2) {                                                        \
            float s0 = (r0 < M) ? rowscale[r0] : 0.f;                        \
            float s1 = (r1 < M) ? rowscale[r1] : 0.f;                        \
            _Pragma("unroll")                                                \
            for (int nt = 0; nt < 8; nt++) {                                 \
                int c = wn * 64 + nt * 8 + tg * 2;                           \
                float* a = acc[mt][nt];                                      \
                if (r0 < M)                                                  \
                    *reinterpret_cast<__half2*>(&Pout[(size_t)r0 * 128 + c]) =           \
                        __floats2half2_rn(a[0] * s0, a[1] * s0);             \
                if (r1 < M)                                                  \
                    *reinterpret_cast<__half2*>(&Pout[(size_t)r1 * 128 + c]) =           \
                        __floats2half2_rn(a[2] * s1, a[3] * s1);             \
            }                                                                \
        } else {                                                             \
            _Pragma("unroll")                                                \
            for (int nt = 0; nt < 8; nt++) {                                 \
                int c = (wn - 2) * 64 + nt * 8 + tg * 2;                     \
                float* a = acc[mt][nt];                                      \
                float b0 = resb[c], b1 = resb[c + 1];                        \
                float o00 = fmaxf(a[0] + b0, 0.f), o01 = fmaxf(a[1] + b1, 0.f);          \
                float o10 = fmaxf(a[2] + b0, 0.f), o11 = fmaxf(a[3] + b1, 0.f);          \
                if (RoutH) {                                                 \
                    if (r0 < M)                                              \
                        *reinterpret_cast<__half2*>(&RoutH[(size_t)r0 * 128 + c]) =      \
                            __floats2half2_rn(o00, o01);                     \
                    if (r1 < M)                                              \
                        *reinterpret_cast<__half2*>(&RoutH[(size_t)r1 * 128 + c]) =      \
                            __floats2half2_rn(o10, o11);                     \
                } else {                                                     \
                    if (r0 < M)                                              \
                        *reinterpret_cast<float2*>(&RoutF[(size_t)r0 * 128 + c]) =       \
                            make_float2(o00, o01);                           \
                    if (r1 < M)                                              \
                        *reinterpret_cast<float2*>(&RoutF[(size_t)r1 * 128 + c]) =       \
                            make_float2(o10, o11);                           \
                }                                                            \
            }                                                                \
        }                                                                    \
    }

// ---- layer 1: X from fp32 global (feats) ----
__global__ __launch_bounds__(512) void k_gemm_l1(
    const float* __restrict__ X, const __half* __restrict__ Wt,
    const float* __restrict__ resb, const float* __restrict__ rowscale,
    __half* __restrict__ Pout, __half* __restrict__ RoutH,
    float* __restrict__ RoutF, int M)
{
    extern __shared__ __half sm[];
    __half* Ws = sm;
    __half* Xs = sm + 256 * WP;
    int tid = threadIdx.x;
    int lane = tid & 31, wid = tid >> 5;
    int wm = wid & 3, wn = wid >> 2;
    int gq = lane >> 2, tg = lane & 3;
    int row0 = blockIdx.x * 128;

#pragma unroll
    for (int i = tid; i < 4096; i += 512) {
        int n = i >> 4, kb = (i & 15) * 8;
        *reinterpret_cast<uint4*>(&Ws[n * WP + kb]) =
            *reinterpret_cast<const uint4*>(&Wt[(size_t)n * 128 + kb]);
    }
    {
        int xr = tid >> 2, xc0 = (tid & 3) * 32;
        int gr = row0 + xr;
        bool rowok = (gr < M);
        const float4* xrow = reinterpret_cast<const float4*>(&X[(size_t)gr * 128 + xc0]);
#pragma unroll
        for (int j = 0; j < 8; j++) {
            float4 v = make_float4(0.f, 0.f, 0.f, 0.f);
            if (rowok) v = xrow[j];
            __half2 h01 = __floats2half2_rn(v.x, v.y);
            __half2 h23 = __floats2half2_rn(v.z, v.w);
            uint2 u;
            u.x = *reinterpret_cast<uint32_t*>(&h01);
            u.y = *reinterpret_cast<uint32_t*>(&h23);
            *reinterpret_cast<uint2*>(&Xs[xr * WP + xc0 + j * 4]) = u;
        }
    }
    __syncthreads();
    GEMM_MAIN_AND_EPI()
}

// ---- layer 2: X = H1 aggregated on the fly from P1/R1/CSR ----
__global__ __launch_bounds__(512) void k_gemm_l2(
    const __half* __restrict__ Ph1, const __half* __restrict__ Rh1,
    const float* __restrict__ aggb, const __half* __restrict__ Wt,
    const float* __restrict__ resb, const float* __restrict__ rowscale,
    __half* __restrict__ Pout, __half* __restrict__ RoutH,
    float* __restrict__ RoutF, int M)
{
    extern __shared__ __half sm[];
    __half* Ws = sm;
    __half* Xs = sm + 256 * WP;
    int tid = threadIdx.x;
    int lane = tid & 31, wid = tid >> 5;
    int wm = wid & 3, wn = wid >> 2;
    int gq = lane >> 2, tg = lane & 3;
    int row0 = blockIdx.x * 128;

#pragma unroll
    for (int i = tid; i < 4096; i += 512) {
        int n = i >> 4, kb = (i & 15) * 8;
        *reinterpret_cast<uint4*>(&Ws[n * WP + kb]) =
            *reinterpret_cast<const uint4*>(&Wt[(size_t)n * 128 + kb]);
    }
    // prologue: each warp aggregates 8 node rows -> Xs (fp16)
    {
        float4 b4 = reinterpret_cast<const float4*>(aggb)[lane];
        for (int s8 = 0; s8 < 8; s8++) {
            int row = wid * 8 + s8;
            int node = row0 + row;
            float4 o = make_float4(0.f, 0.f, 0.f, 0.f);
            if (node < M) {
                int e0 = g_row_ptr[node], e1 = g_row_ptr[node + 1];
                float4 acc = gather_row(Ph1, e0, e1, lane);
                float inn = g_in_norm[node];
                uint2 rv = reinterpret_cast<const uint2*>(Rh1)[(size_t)node * 32 + lane];
                float2 r0 = __half22float2(*reinterpret_cast<__half2*>(&rv.x));
                float2 r1 = __half22float2(*reinterpret_cast<__half2*>(&rv.y));
                o.x = fmaxf(fmaf(acc.x, inn, b4.x), 0.f) + r0.x;
                o.y = fmaxf(fmaf(acc.y, inn, b4.y), 0.f) + r0.y;
                o.z = fmaxf(fmaf(acc.z, inn, b4.z), 0.f) + r1.x;
                o.w = fmaxf(fmaf(acc.w, inn, b4.w), 0.f) + r1.y;
            }
            __half2 h01 = __floats2half2_rn(o.x, o.y);
            __half2 h23 = __floats2half2_rn(o.z, o.w);
            uint2 u;
            u.x = *reinterpret_cast<uint32_t*>(&h01);
            u.y = *reinterpret_cast<uint32_t*>(&h23);
            *reinterpret_cast<uint2*>(&Xs[row * WP + lane * 4]) = u;
        }
    }
    __syncthreads();
    GEMM_MAIN_AND_EPI()
}

// ---------------------------------------------------------------------------
// readout with agg2 inline: warp per graph; per node compute
// h = relu(gather(P2)*in_norm + b2) + R2, then weighted-sum + max.
// ---------------------------------------------------------------------------
__global__ void k_readout2(const __half* __restrict__ Ph2, const float* __restrict__ R2f,
                           const float* __restrict__ aggb,
                           const int* __restrict__ gid,
                           const float* __restrict__ awW, const float* __restrict__ awb,
                           float* __restrict__ X2, int ldx, int Nn, int Bg)
{
    int g = (int)((blockIdx.x * (size_t)blockDim.x + threadIdx.x) >> 5);
    int lane = threadIdx.x & 31;
    if (g >= Bg) return;
    int lo = 0, hi = Nn;
    while (lo < hi) { int mid = (lo + hi) >> 1; if (gid[mid] < g) lo = mid + 1; else hi = mid; }
    int lo2 = lo, hi2 = Nn;
    while (lo2 < hi2) { int mid = (lo2 + hi2) >> 1; if (gid[mid] < g + 1) lo2 = mid + 1; else hi2 = mid; }

    float4 a4 = reinterpret_cast<const float4*>(awW)[lane];
    float4 b4 = reinterpret_cast<const float4*>(aggb)[lane];
    float ab = awb[0];
    float4 s  = make_float4(0.f, 0.f, 0.f, 0.f);
    float4 mx = make_float4(0.f, 0.f, 0.f, 0.f);   // h >= 0
    const float4* R4 = reinterpret_cast<const float4*>(R2f);
    for (int i = lo; i < lo2; i++) {
        int e0 = g_row_ptr[i], e1 = g_row_ptr[i + 1];
        float4 acc = gather_row(Ph2, e0, e1, lane);
        float inn = g_in_norm[i];
        float4 r = R4[(size_t)i * 32 + lane];
        float4 h;
        h.x = fmaxf(fmaf(acc.x, inn, b4.x), 0.f) + r.x;
        h.y = fmaxf(fmaf(acc.y, inn, b4.y), 0.f) + r.y;
        h.z = fmaxf(fmaf(acc.z, inn, b4.z), 0.f) + r.z;
        h.w = fmaxf(fmaf(acc.w, inn, b4.w), 0.f) + r.w;
        float d = h.x * a4.x + h.y * a4.y + h.z * a4.z + h.w * a4.w;
#pragma unroll
        for (int o = 16; o; o >>= 1) d += __shfl_xor_sync(0xffffffffu, d, o);
        float aw = 1.f / (1.f + expf(-(d + ab)));
        s.x += aw * h.x; s.y += aw * h.y; s.z += aw * h.z; s.w += aw * h.w;
        mx.x = fmaxf(mx.x, h.x); mx.y = fmaxf(mx.y, h.y);
        mx.z = fmaxf(mx.z, h.z); mx.w = fmaxf(mx.w, h.w);
    }
    *reinterpret_cast<float4*>(&X2[(size_t)g * ldx + lane * 4]) = s;
    *reinterpret_cast<float4*>(&X2[(size_t)g * ldx + 128 + lane * 4]) = mx;
}

// ---------------------------------------------------------------------------
// MLP GEMM (fp32 SIMT, k-blocked float4 inner loop, 16 rows/block)
// ---------------------------------------------------------------------------
#define MLPR 16
__global__ __launch_bounds__(128) void k_mlp(
    const float* __restrict__ A, int lda,
    const float* __restrict__ W, const float* __restrict__ bias,
    const float* __restrict__ gamma, const float* __restrict__ beta, int mode,
    float* __restrict__ out1, int ldo1, float* __restrict__ out2, int ldo2,
    int M, int K, int Nc)
{
    __shared__ float As[MLPR][36];
    __shared__ float Ws[32][128];
    int row0 = blockIdx.x * MLPR;
    int n0 = blockIdx.y * 128;
    int col = threadIdx.x;
    float acc[MLPR];
#pragma unroll
    for (int r = 0; r < MLPR; r++) acc[r] = 0.f;

    for (int k0 = 0; k0 < K; k0 += 32) {
        for (int i = threadIdx.x; i < MLPR * 32; i += 128) {
            int r = i >> 5, k = i & 31;
            int gk = k0 + k, gr = row0 + r;
            As[r][k] = (gk < K && gr < M) ? A[(size_t)gr * lda + gk] : 0.f;
        }
        for (int i = threadIdx.x; i < 4096; i += 128) {
            int kr = i >> 7, c = i & 127;
            int gk = k0 + kr, gc = n0 + c;
            Ws[kr][c] = (gk < K && gc < Nc) ? W[(size_t)gk * Nc + gc] : 0.f;
        }
        __syncthreads();
#pragma unroll
        for (int kb = 0; kb < 8; kb++) {
            float w0 = Ws[kb * 4 + 0][col];
            float w1 = Ws[kb * 4 + 1][col];
            float w2 = Ws[kb * 4 + 2][col];
            float w3 = Ws[kb * 4 + 3][col];
#pragma unroll
            for (int r = 0; r < MLPR; r++) {
                float4 a = *reinterpret_cast<const float4*>(&As[r][kb * 4]);
                acc[r] = fmaf(a.x, w0, acc[r]);
                acc[r] = fmaf(a.y, w1, acc[r]);
                acc[r] = fmaf(a.z, w2, acc[r]);
                acc[r] = fmaf(a.w, w3, acc[r]);
            }
        }
        __syncthreads();
    }
    int gc = n0 + col;
    if (gc >= Nc) return;
    float bv = bias ? bias[gc] : 0.f;
    float gam = (mode == 1) ? gamma[gc] * BN_INV : 0.f;
    float bet = (mode == 1) ? beta[gc] : 0.f;
#pragma unroll
    for (int r = 0; r < MLPR; r++) {
        int gr = row0 + r;
        if (gr >= M) break;
        float v = acc[r] + bv;
        if (mode == 1) v = fmaxf(v, 0.f) * gam + bet;
        out1[(size_t)gr * ldo1 + gc] = v;
        if (out2) out2[(size_t)gr * ldo2 + gc] = v;
    }
}

// ---------------------------------------------------------------------------
// host
// ---------------------------------------------------------------------------
extern "C" void kernel_launch(void* const* d_in, const int* in_sizes, int n_in,
                              void* d_out, int out_size)
{
    const float* feats  = (const float*)d_in[0];
    const int*   src    = (const int*)  d_in[1];
    const int*   dst    = (const int*)  d_in[2];
    const int*   gid    = (const int*)  d_in[3];
    const float* W1     = (const float*)d_in[4];
    const float* b1     = (const float*)d_in[5];
    const float* resW1  = (const float*)d_in[6];
    const float* resb1  = (const float*)d_in[7];
    const float* W2     = (const float*)d_in[8];
    const float* b2     = (const float*)d_in[9];
    const float* resW2  = (const float*)d_in[10];
    const float* resb2  = (const float*)d_in[11];
    const float* awW    = (const float*)d_in[12];
    const float* awb    = (const float*)d_in[13];
    const float* orW1   = (const float*)d_in[14];
    const float* orb1   = (const float*)d_in[15];
    const float* org    = (const float*)d_in[16];
    const float* orbeta = (const float*)d_in[17];
    const float* orW2   = (const float*)d_in[18];
    const float* orb2   = (const float*)d_in[19];
    const float* scW1   = (const float*)d_in[20];
    const float* scb1   = (const float*)d_in[21];
    const float* scg    = (const float*)d_in[22];
    const float* scbeta = (const float*)d_in[23];
    const float* scW2   = (const float*)d_in[24];
    const float* scb2   = (const float*)d_in[25];

    int N  = in_sizes[0] / HD;
    int E  = in_sizes[1];
    int T1 = in_sizes[19];
    int T2 = in_sizes[25];
    int MH = in_sizes[15];
    int B  = out_size / (T1 + T2);
    int ldx = 832;

    float* out    = (float*)d_out;
    float* out_sc = out + (size_t)B * T1;

    void *pPh1, *pRh1, *pPh2, *pR2f, *pZ, *pX2, *pON, *pDS, *pDD, *pWt;
    cudaGetSymbolAddress(&pPh1, g_Ph1);
    cudaGetSymbolAddress(&pRh1, g_Rh1);
    cudaGetSymbolAddress(&pPh2, g_Ph2);
    cudaGetSymbolAddress(&pR2f, g_R2f);
    cudaGetSymbolAddress(&pZ,   g_Z);
    cudaGetSymbolAddress(&pX2,  g_X2);
    cudaGetSymbolAddress(&pON,  g_out_norm);
    cudaGetSymbolAddress(&pDS,  g_deg_src);
    cudaGetSymbolAddress(&pDD,  g_deg_dst);
    cudaGetSymbolAddress(&pWt,  g_Wt);
    __half* Ph1 = (__half*)pPh1;
    __half* Rh1 = (__half*)pRh1;
    __half* Ph2 = (__half*)pPh2;
    float*  R2f = (float*)pR2f;
    float*  Z   = (float*)pZ;
    float*  X2  = (float*)pX2;
    float*  ONm = (float*)pON;
    __half* Wt0 = (__half*)pWt;
    __half* Wt1 = Wt0 + (size_t)256 * 128;

    cudaFuncSetAttribute(k_gemm_l1, cudaFuncAttributeMaxDynamicSharedMemorySize, GEMM_SMEM);
    cudaFuncSetAttribute(k_gemm_l2, cudaFuncAttributeMaxDynamicSharedMemorySize, GEMM_SMEM);

    int eb  = (E + 255) / 256;
    int nb  = (N + SCAN_CHUNK - 1) / SCAN_CHUNK;
    int gb  = (N + 127) / 128;

    // launches: 1 memset, 2 memset, 3 wconv, 4 deg, 5 normchunk,
    //           6 gemm_l1 <- ncu skip-5 profile slot
    cudaMemsetAsync(pDS, 0, (size_t)N * sizeof(int), 0);
    cudaMemsetAsync(pDD, 0, (size_t)N * sizeof(int), 0);
    k_wconv<<<(2 * 256 * 128 + 255) / 256, 256>>>(W1, resW1, W2, resW2);
    k_deg<<<eb, 256>>>(src, dst, E);
    k_normchunk<<<nb, 256>>>(N);

    k_gemm_l1<<<gb, 512, GEMM_SMEM>>>(feats, Wt0, resb1, ONm, Ph1, Rh1, nullptr, N);

    k_scan_bsums<<<1, 256>>>(nb, N);
    k_scan_final<<<nb, 256>>>(N);
    k_build<<<eb, 256>>>(src, dst, E);

    k_gemm_l2<<<gb, 512, GEMM_SMEM>>>(Ph1, Rh1, b1, Wt1, resb2, ONm, Ph2, nullptr, R2f, N);

    k_readout2<<<(B + 7) / 8, 256>>>(Ph2, R2f, b2, gid, awW, awb, X2, ldx, N, B);

    dim3 gm1((B + MLPR - 1) / MLPR, (MH + 127) / 128);
    k_mlp<<<gm1, 128>>>(X2, ldx, orW1, orb1, org, orbeta, 1,
                        Z, MH, nullptr, 0, B, 256, MH);
    dim3 gm2((B + MLPR - 1) / MLPR, (T1 + 127) / 128);
    k_mlp<<<gm2, 128>>>(Z, MH, orW2, orb2, nullptr, nullptr, 0,
                        out, T1, X2 + 256, ldx, B, MH, T1);
    dim3 gm3((B + MLPR - 1) / MLPR, (MH + 127) / 128);
    k_mlp<<<gm3, 128>>>(X2, ldx, scW1, scb1, scg, scbeta, 1,
                        Z, MH, nullptr, 0, B, 256 + T1, MH);
    dim3 gm4((B + MLPR - 1) / MLPR, (T2 + 127) / 128);
    k_mlp<<<gm4, 128>>>(Z, MH, scW2, scb2, nullptr, nullptr, 0,
                        out_sc, T2, nullptr, 0, B, MH, T2);
}

// round 9
// speedup vs baseline: 1.2892x; 1.2892x over previous
#include <cuda_runtime.h>
#include <cuda_fp16.h>
#include <math.h>
#include <stdint.h>

// ---------------------------------------------------------------------------
// GCNJointPredictor, round 9 (revert R7/R8 fusion regression to R6 structure):
//  - dedicated warp-per-node k_agg x2 (parallelism >> fused variants)
//  - H1 stored fp16 (error-free; gemm2 reads fp16 X), H2 fp32 for readout
//  - keep: fp16 GEMM (one barrier, W+X smem resident), normchunk fusion,
//    MLPR=16 MLP, atomic-free readout
// ---------------------------------------------------------------------------

#define NMAX 100000
#define EMAX 3200000
#define BMAX 4096
#define HD   128
#define BN_INV 0.9999950000374997f
#define SCAN_CHUNK 1024

// ---- scratch (device globals) ----
__device__ __align__(16) __half g_Ph[(size_t)NMAX * HD];    // P (both layers)
__device__ __align__(16) float  g_Rf[(size_t)NMAX * HD];    // R (both layers)
__device__ __align__(16) __half g_Hh[(size_t)NMAX * HD];    // H1 fp16
__device__ __align__(16) float  g_Hf[(size_t)NMAX * HD];    // H2 fp32
__device__ __align__(16) float  g_Z[(size_t)BMAX * HD];
__device__ __align__(16) float  g_X2[(size_t)BMAX * 832];
__device__ __align__(16) __half g_Wt[2][256 * 128];         // [layer][n][k] fp16
__device__ int   g_deg_src[NMAX];
__device__ int   g_deg_dst[NMAX];
__device__ float g_out_norm[NMAX];
__device__ float g_in_norm[NMAX];
__device__ int   g_row_ptr[NMAX + 1];
__device__ int   g_cursor[NMAX];
__device__ int   g_esrc[EMAX];
__device__ int   g_bsum[256];
__device__ int   g_boff[256];

// ---------------------------------------------------------------------------
// one-shot weight transpose to fp16: Wt[n][k] = half(W[k][n])
// ---------------------------------------------------------------------------
__global__ void k_wconv(const float* __restrict__ W1, const float* __restrict__ rW1,
                        const float* __restrict__ W2, const float* __restrict__ rW2)
{
    int i = blockIdx.x * blockDim.x + threadIdx.x;
    if (i >= 2 * 256 * 128) return;
    int layer = i >> 15;
    int j = i & 32767;
    int n = j >> 7, k = j & 127;
    const float* src = (layer == 0) ? ((n < 128) ? W1 : rW1)
                                    : ((n < 128) ? W2 : rW2);
    g_Wt[layer][(size_t)n * 128 + k] = __float2half(src[(size_t)k * 128 + (n & 127)]);
}

__global__ void k_deg(const int* __restrict__ src, const int* __restrict__ dst, int E) {
    int e = blockIdx.x * blockDim.x + threadIdx.x;
    if (e < E) {
        atomicAdd(&g_deg_src[src[e]], 1);
        atomicAdd(&g_deg_dst[dst[e]], 1);
    }
}

// fused: norms + per-chunk sum of deg_dst
__global__ void k_normchunk(int Nn) {
    __shared__ int sdata[256];
    int base = blockIdx.x * SCAN_CHUNK;
    int s = 0;
    for (int i = threadIdx.x; i < SCAN_CHUNK; i += 256) {
        int idx = base + i;
        if (idx < Nn) {
            int ds = g_deg_src[idx], dd = g_deg_dst[idx];
            g_out_norm[idx] = rsqrtf((float)max(ds, 1));
            g_in_norm[idx]  = rsqrtf((float)max(dd, 1));
            s += dd;
        }
    }
    sdata[threadIdx.x] = s;
    __syncthreads();
    for (int off = 128; off > 0; off >>= 1) {
        if (threadIdx.x < off) sdata[threadIdx.x] += sdata[threadIdx.x + off];
        __syncthreads();
    }
    if (threadIdx.x == 0) g_bsum[blockIdx.x] = sdata[0];
}

__global__ void k_scan_bsums(int nb, int Nn) {
    __shared__ int s[256];
    int t = threadIdx.x;
    int v = (t < nb) ? g_bsum[t] : 0;
    s[t] = v;
    __syncthreads();
#pragma unroll
    for (int d = 1; d < 256; d <<= 1) {
        int x = (t >= d) ? s[t - d] : 0;
        __syncthreads();
        s[t] += x;
        __syncthreads();
    }
    if (t < nb) g_boff[t] = s[t] - v;
    if (t == 0) g_row_ptr[Nn] = s[255];
}

__global__ void k_scan_final(int Nn) {
    __shared__ int s0[SCAN_CHUNK];
    __shared__ int s1[SCAN_CHUNK];
    int base = blockIdx.x * SCAN_CHUNK;
    for (int i = threadIdx.x; i < SCAN_CHUNK; i += 256) {
        int idx = base + i;
        s0[i] = (idx < Nn) ? g_deg_dst[idx] : 0;
    }
    __syncthreads();
    int* a = s0; int* b = s1;
    for (int d = 1; d < SCAN_CHUNK; d <<= 1) {
        for (int i = threadIdx.x; i < SCAN_CHUNK; i += 256)
            b[i] = a[i] + (i >= d ? a[i - d] : 0);
        __syncthreads();
        int* t = a; a = b; b = t;
    }
    int off = g_boff[blockIdx.x];
    for (int i = threadIdx.x; i < SCAN_CHUNK; i += 256) {
        int idx = base + i;
        if (idx < Nn) {
            int ex = off + (i > 0 ? a[i - 1] : 0);
            g_row_ptr[idx] = ex;
            g_cursor[idx]  = ex;
        }
    }
}

__global__ void k_build(const int* __restrict__ src, const int* __restrict__ dst, int E) {
    int e = blockIdx.x * blockDim.x + threadIdx.x;
    if (e < E) {
        int p = atomicAdd(&g_cursor[dst[e]], 1);
        g_esrc[p] = src[e];
    }
}

// ---------------------------------------------------------------------------
// fused fp16 tensor-core GEMM core (one barrier, W+X smem resident)
// block 128 rows x 256 cols, 512 thr (16 warps 4Mx4N), warp tile 32x64
// Epilogue: cols [0,128) -> Pout fp16 * rowscale; [128,256) -> RoutF relu fp32
// ---------------------------------------------------------------------------
#define WP 136
#define GEMM_SMEM ((256 * WP + 128 * WP) * 2)   // 104448 bytes

#define MMA_F16(c, a0, a1, a2, a3, b0, b1)                                   \
    asm volatile(                                                            \
        "mma.sync.aligned.m16n8k16.row.col.f32.f16.f16.f32 "                 \
        "{%0,%1,%2,%3}, {%4,%5,%6,%7}, {%8,%9}, {%0,%1,%2,%3};"              \
        : "+f"((c)[0]), "+f"((c)[1]), "+f"((c)[2]), "+f"((c)[3])             \
        : "r"(a0), "r"(a1), "r"(a2), "r"(a3), "r"(b0), "r"(b1))

#define GEMM_MAIN_AND_EPI()                                                  \
    float acc[2][8][4];                                                      \
    _Pragma("unroll")                                                        \
    for (int mt = 0; mt < 2; mt++)                                           \
        _Pragma("unroll")                                                    \
        for (int nt = 0; nt < 8; nt++)                                       \
            _Pragma("unroll")                                                \
            for (int q = 0; q < 4; q++) acc[mt][nt][q] = 0.f;                \
    _Pragma("unroll")                                                        \
    for (int c = 0; c < 8; c++) {                                            \
        int kk = c * 16;                                                     \
        uint32_t a[2][4];                                                    \
        _Pragma("unroll")                                                    \
        for (int mt = 0; mt < 2; mt++) {                                     \
            int r = wm * 32 + mt * 16 + gq;                                  \
            a[mt][0] = *reinterpret_cast<uint32_t*>(&Xs[r * WP + kk + tg * 2]);          \
            a[mt][1] = *reinterpret_cast<uint32_t*>(&Xs[(r + 8) * WP + kk + tg * 2]);    \
            a[mt][2] = *reinterpret_cast<uint32_t*>(&Xs[r * WP + kk + 8 + tg * 2]);      \
            a[mt][3] = *reinterpret_cast<uint32_t*>(&Xs[(r + 8) * WP + kk + 8 + tg * 2]);\
        }                                                                    \
        _Pragma("unroll")                                                    \
        for (int nt = 0; nt < 8; nt++) {                                     \
            int nb = wn * 64 + nt * 8 + gq;                                  \
            uint32_t b0 = *reinterpret_cast<uint32_t*>(&Ws[nb * WP + kk + tg * 2]);      \
            uint32_t b1 = *reinterpret_cast<uint32_t*>(&Ws[nb * WP + kk + 8 + tg * 2]);  \
            _Pragma("unroll")                                                \
            for (int mt = 0; mt < 2; mt++)                                   \
                MMA_F16(acc[mt][nt], a[mt][0], a[mt][1], a[mt][2], a[mt][3], b0, b1);    \
        }                                                                    \
    }                                                                        \
    _Pragma("unroll")                                                        \
    for (int mt = 0; mt < 2; mt++) {                                         \
        int r0 = row0 + wm * 32 + mt * 16 + gq;                              \
        int r1 = r0 + 8;                                                     \
        if (wn < 2) {                                                        \
            float s0 = (r0 < M) ? rowscale[r0] : 0.f;                        \
            float s1 = (r1 < M) ? rowscale[r1] : 0.f;                        \
            _Pragma("unroll")                                                \
            for (int nt = 0; nt < 8; nt++) {                                 \
                int c = wn * 64 + nt * 8 + tg * 2;                           \
                float* a = acc[mt][nt];                                      \
                if (r0 < M)                                                  \
                    *reinterpret_cast<__half2*>(&Pout[(size_t)r0 * 128 + c]) =           \
                        __floats2half2_rn(a[0] * s0, a[1] * s0);             \
                if (r1 < M)                                                  \
                    *reinterpret_cast<__half2*>(&Pout[(size_t)r1 * 128 + c]) =           \
                        __floats2half2_rn(a[2] * s1, a[3] * s1);             \
            }                                                                \
        } else {                                                             \
            _Pragma("unroll")                                                \
            for (int nt = 0; nt < 8; nt++) {                                 \
                int c = (wn - 2) * 64 + nt * 8 + tg * 2;                     \
                float* a = acc[mt][nt];                                      \
                float b0 = resb[c], b1 = resb[c + 1];                        \
                if (r0 < M)                                                  \
                    *reinterpret_cast<float2*>(&RoutF[(size_t)r0 * 128 + c]) =           \
                        make_float2(fmaxf(a[0] + b0, 0.f), fmaxf(a[1] + b1, 0.f));       \
                if (r1 < M)                                                  \
                    *reinterpret_cast<float2*>(&RoutF[(size_t)r1 * 128 + c]) =           \
                        make_float2(fmaxf(a[2] + b0, 0.f), fmaxf(a[3] + b1, 0.f));       \
            }                                                                \
        }                                                                    \
    }

// ---- layer 1: X from fp32 global ----
__global__ __launch_bounds__(512) void k_gemm_l1(
    const float* __restrict__ X, const __half* __restrict__ Wt,
    const float* __restrict__ resb, const float* __restrict__ rowscale,
    __half* __restrict__ Pout, float* __restrict__ RoutF, int M)
{
    extern __shared__ __half sm[];
    __half* Ws = sm;
    __half* Xs = sm + 256 * WP;
    int tid = threadIdx.x;
    int lane = tid & 31, wid = tid >> 5;
    int wm = wid & 3, wn = wid >> 2;
    int gq = lane >> 2, tg = lane & 3;
    int row0 = blockIdx.x * 128;

#pragma unroll
    for (int i = tid; i < 4096; i += 512) {
        int n = i >> 4, kb = (i & 15) * 8;
        *reinterpret_cast<uint4*>(&Ws[n * WP + kb]) =
            *reinterpret_cast<const uint4*>(&Wt[(size_t)n * 128 + kb]);
    }
    {
        int xr = tid >> 2, xc0 = (tid & 3) * 32;
        int gr = row0 + xr;
        bool rowok = (gr < M);
        const float4* xrow = reinterpret_cast<const float4*>(&X[(size_t)gr * 128 + xc0]);
#pragma unroll
        for (int j = 0; j < 8; j++) {
            float4 v = make_float4(0.f, 0.f, 0.f, 0.f);
            if (rowok) v = xrow[j];
            __half2 h01 = __floats2half2_rn(v.x, v.y);
            __half2 h23 = __floats2half2_rn(v.z, v.w);
            uint2 u;
            u.x = *reinterpret_cast<uint32_t*>(&h01);
            u.y = *reinterpret_cast<uint32_t*>(&h23);
            *reinterpret_cast<uint2*>(&Xs[xr * WP + xc0 + j * 4]) = u;
        }
    }
    __syncthreads();
    GEMM_MAIN_AND_EPI()
}

// ---- layer 2: X from fp16 global (H1) ----
__global__ __launch_bounds__(512) void k_gemm_l2h(
    const __half* __restrict__ Xh, const __half* __restrict__ Wt,
    const float* __restrict__ resb, const float* __restrict__ rowscale,
    __half* __restrict__ Pout, float* __restrict__ RoutF, int M)
{
    extern __shared__ __half sm[];
    __half* Ws = sm;
    __half* Xs = sm + 256 * WP;
    int tid = threadIdx.x;
    int lane = tid & 31, wid = tid >> 5;
    int wm = wid & 3, wn = wid >> 2;
    int gq = lane >> 2, tg = lane & 3;
    int row0 = blockIdx.x * 128;

#pragma unroll
    for (int i = tid; i < 4096; i += 512) {
        int n = i >> 4, kb = (i & 15) * 8;
        *reinterpret_cast<uint4*>(&Ws[n * WP + kb]) =
            *reinterpret_cast<const uint4*>(&Wt[(size_t)n * 128 + kb]);
    }
    {
        // 128 rows x 128 halves = 2048 uint4; 512 thr x 4
        int xr = tid >> 2, xc0 = (tid & 3) * 32;
        int gr = row0 + xr;
        bool rowok = (gr < M);
        const uint4* xrow = reinterpret_cast<const uint4*>(&Xh[(size_t)gr * 128 + xc0]);
#pragma unroll
        for (int j = 0; j < 4; j++) {
            uint4 v = make_uint4(0u, 0u, 0u, 0u);
            if (rowok) v = xrow[j];
            *reinterpret_cast<uint4*>(&Xs[xr * WP + xc0 + j * 8]) = v;
        }
    }
    __syncthreads();
    GEMM_MAIN_AND_EPI()
}

// ---------------------------------------------------------------------------
// aggregation: warp per node, fp16 P rows, 4-edge unroll, fp32 accumulate
// h = relu(sum P[u] * in_norm + b) + R ;  store fp16 (layer1) or fp32 (layer2)
// ---------------------------------------------------------------------------
__device__ __forceinline__ float4 agg_node(const __half* __restrict__ P,
                                           const float* __restrict__ R,
                                           float4 b, int w, int lane)
{
    int e0 = g_row_ptr[w], e1 = g_row_ptr[w + 1];
    const uint2* P2 = reinterpret_cast<const uint2*>(P);
    float4 acc = make_float4(0.f, 0.f, 0.f, 0.f);
    int e = e0;
#define ACCV(v) { \
    float2 p0 = __half22float2(*reinterpret_cast<__half2*>(&(v).x)); \
    float2 p1 = __half22float2(*reinterpret_cast<__half2*>(&(v).y)); \
    acc.x += p0.x; acc.y += p0.y; acc.z += p1.x; acc.w += p1.y; }
    for (; e + 3 < e1; e += 4) {
        int u0 = g_esrc[e],     u1 = g_esrc[e + 1];
        int u2 = g_esrc[e + 2], u3 = g_esrc[e + 3];
        uint2 v0 = P2[(size_t)u0 * 32 + lane];
        uint2 v1 = P2[(size_t)u1 * 32 + lane];
        uint2 v2 = P2[(size_t)u2 * 32 + lane];
        uint2 v3 = P2[(size_t)u3 * 32 + lane];
        ACCV(v0); ACCV(v1); ACCV(v2); ACCV(v3);
    }
    for (; e < e1; e++) {
        int u = g_esrc[e];
        uint2 v = P2[(size_t)u * 32 + lane];
        ACCV(v);
    }
#undef ACCV
    float inn = g_in_norm[w];
    float4 r = reinterpret_cast<const float4*>(R)[(size_t)w * 32 + lane];
    float4 o;
    o.x = fmaxf(fmaf(acc.x, inn, b.x), 0.f) + r.x;
    o.y = fmaxf(fmaf(acc.y, inn, b.y), 0.f) + r.y;
    o.z = fmaxf(fmaf(acc.z, inn, b.z), 0.f) + r.z;
    o.w = fmaxf(fmaf(acc.w, inn, b.w), 0.f) + r.w;
    return o;
}

__global__ void k_agg_h(const __half* __restrict__ P, const float* __restrict__ R,
                        const float* __restrict__ bias, int Nn, __half* __restrict__ out)
{
    int w = (int)((blockIdx.x * (size_t)blockDim.x + threadIdx.x) >> 5);
    int lane = threadIdx.x & 31;
    if (w >= Nn) return;
    float4 b = reinterpret_cast<const float4*>(bias)[lane];
    float4 o = agg_node(P, R, b, w, lane);
    __half2 h01 = __floats2half2_rn(o.x, o.y);
    __half2 h23 = __floats2half2_rn(o.z, o.w);
    uint2 u;
    u.x = *reinterpret_cast<uint32_t*>(&h01);
    u.y = *reinterpret_cast<uint32_t*>(&h23);
    reinterpret_cast<uint2*>(out)[(size_t)w * 32 + lane] = u;
}

__global__ void k_agg_f(const __half* __restrict__ P, const float* __restrict__ R,
                        const float* __restrict__ bias, int Nn, float* __restrict__ out)
{
    int w = (int)((blockIdx.x * (size_t)blockDim.x + threadIdx.x) >> 5);
    int lane = threadIdx.x & 31;
    if (w >= Nn) return;
    float4 b = reinterpret_cast<const float4*>(bias)[lane];
    float4 o = agg_node(P, R, b, w, lane);
    reinterpret_cast<float4*>(out)[(size_t)w * 32 + lane] = o;
}

// ---------------------------------------------------------------------------
// readout: warp per graph, binary search on sorted gid, no atomics
// ---------------------------------------------------------------------------
__global__ void k_readout(const float* __restrict__ H, const int* __restrict__ gid,
                          const float* __restrict__ awW, const float* __restrict__ awb,
                          float* __restrict__ X2, int ldx, int Nn, int Bg)
{
    int g = (int)((blockIdx.x * (size_t)blockDim.x + threadIdx.x) >> 5);
    int lane = threadIdx.x & 31;
    if (g >= Bg) return;
    int lo = 0, hi = Nn;
    while (lo < hi) { int mid = (lo + hi) >> 1; if (gid[mid] < g) lo = mid + 1; else hi = mid; }
    int lo2 = lo, hi2 = Nn;
    while (lo2 < hi2) { int mid = (lo2 + hi2) >> 1; if (gid[mid] < g + 1) lo2 = mid + 1; else hi2 = mid; }

    float4 a = reinterpret_cast<const float4*>(awW)[lane];
    float ab = awb[0];
    float4 s  = make_float4(0.f, 0.f, 0.f, 0.f);
    float4 mx = make_float4(0.f, 0.f, 0.f, 0.f);   // h >= 0
    const float4* H4 = reinterpret_cast<const float4*>(H);
    for (int i = lo; i < lo2; i++) {
        float4 h = H4[(size_t)i * 32 + lane];
        float d = h.x * a.x + h.y * a.y + h.z * a.z + h.w * a.w;
#pragma unroll
        for (int o = 16; o; o >>= 1) d += __shfl_xor_sync(0xffffffffu, d, o);
        float aw = 1.f / (1.f + expf(-(d + ab)));
        s.x += aw * h.x; s.y += aw * h.y; s.z += aw * h.z; s.w += aw * h.w;
        mx.x = fmaxf(mx.x, h.x); mx.y = fmaxf(mx.y, h.y);
        mx.z = fmaxf(mx.z, h.z); mx.w = fmaxf(mx.w, h.w);
    }
    *reinterpret_cast<float4*>(&X2[(size_t)g * ldx + lane * 4]) = s;
    *reinterpret_cast<float4*>(&X2[(size_t)g * ldx + 128 + lane * 4]) = mx;
}

// ---------------------------------------------------------------------------
// MLP GEMM (fp32 SIMT, k-blocked float4 inner loop, 16 rows/block)
// ---------------------------------------------------------------------------
#define MLPR 16
__global__ __launch_bounds__(128) void k_mlp(
    const float* __restrict__ A, int lda,
    const float* __restrict__ W, const float* __restrict__ bias,
    const float* __restrict__ gamma, const float* __restrict__ beta, int mode,
    float* __restrict__ out1, int ldo1, float* __restrict__ out2, int ldo2,
    int M, int K, int Nc)
{
    __shared__ float As[MLPR][36];
    __shared__ float Ws[32][128];
    int row0 = blockIdx.x * MLPR;
    int n0 = blockIdx.y * 128;
    int col = threadIdx.x;
    float acc[MLPR];
#pragma unroll
    for (int r = 0; r < MLPR; r++) acc[r] = 0.f;

    for (int k0 = 0; k0 < K; k0 += 32) {
        for (int i = threadIdx.x; i < MLPR * 32; i += 128) {
            int r = i >> 5, k = i & 31;
            int gk = k0 + k, gr = row0 + r;
            As[r][k] = (gk < K && gr < M) ? A[(size_t)gr * lda + gk] : 0.f;
        }
        for (int i = threadIdx.x; i < 4096; i += 128) {
            int kr = i >> 7, c = i & 127;
            int gk = k0 + kr, gc = n0 + c;
            Ws[kr][c] = (gk < K && gc < Nc) ? W[(size_t)gk * Nc + gc] : 0.f;
        }
        __syncthreads();
#pragma unroll
        for (int kb = 0; kb < 8; kb++) {
            float w0 = Ws[kb * 4 + 0][col];
            float w1 = Ws[kb * 4 + 1][col];
            float w2 = Ws[kb * 4 + 2][col];
            float w3 = Ws[kb * 4 + 3][col];
#pragma unroll
            for (int r = 0; r < MLPR; r++) {
                float4 a = *reinterpret_cast<const float4*>(&As[r][kb * 4]);
                acc[r] = fmaf(a.x, w0, acc[r]);
                acc[r] = fmaf(a.y, w1, acc[r]);
                acc[r] = fmaf(a.z, w2, acc[r]);
                acc[r] = fmaf(a.w, w3, acc[r]);
            }
        }
        __syncthreads();
    }
    int gc = n0 + col;
    if (gc >= Nc) return;
    float bv = bias ? bias[gc] : 0.f;
    float gam = (mode == 1) ? gamma[gc] * BN_INV : 0.f;
    float bet = (mode == 1) ? beta[gc] : 0.f;
#pragma unroll
    for (int r = 0; r < MLPR; r++) {
        int gr = row0 + r;
        if (gr >= M) break;
        float v = acc[r] + bv;
        if (mode == 1) v = fmaxf(v, 0.f) * gam + bet;
        out1[(size_t)gr * ldo1 + gc] = v;
        if (out2) out2[(size_t)gr * ldo2 + gc] = v;
    }
}

// ---------------------------------------------------------------------------
// host
// ---------------------------------------------------------------------------
extern "C" void kernel_launch(void* const* d_in, const int* in_sizes, int n_in,
                              void* d_out, int out_size)
{
    const float* feats  = (const float*)d_in[0];
    const int*   src    = (const int*)  d_in[1];
    const int*   dst    = (const int*)  d_in[2];
    const int*   gid    = (const int*)  d_in[3];
    const float* W1     = (const float*)d_in[4];
    const float* b1     = (const float*)d_in[5];
    const float* resW1  = (const float*)d_in[6];
    const float* resb1  = (const float*)d_in[7];
    const float* W2     = (const float*)d_in[8];
    const float* b2     = (const float*)d_in[9];
    const float* resW2  = (const float*)d_in[10];
    const float* resb2  = (const float*)d_in[11];
    const float* awW    = (const float*)d_in[12];
    const float* awb    = (const float*)d_in[13];
    const float* orW1   = (const float*)d_in[14];
    const float* orb1   = (const float*)d_in[15];
    const float* org    = (const float*)d_in[16];
    const float* orbeta = (const float*)d_in[17];
    const float* orW2   = (const float*)d_in[18];
    const float* orb2   = (const float*)d_in[19];
    const float* scW1   = (const float*)d_in[20];
    const float* scb1   = (const float*)d_in[21];
    const float* scg    = (const float*)d_in[22];
    const float* scbeta = (const float*)d_in[23];
    const float* scW2   = (const float*)d_in[24];
    const float* scb2   = (const float*)d_in[25];

    int N  = in_sizes[0] / HD;
    int E  = in_sizes[1];
    int T1 = in_sizes[19];
    int T2 = in_sizes[25];
    int MH = in_sizes[15];
    int B  = out_size / (T1 + T2);
    int ldx = 832;

    float* out    = (float*)d_out;
    float* out_sc = out + (size_t)B * T1;

    void *pPh, *pRf, *pHh, *pHf, *pZ, *pX2, *pON, *pDS, *pDD, *pWt;
    cudaGetSymbolAddress(&pPh, g_Ph);
    cudaGetSymbolAddress(&pRf, g_Rf);
    cudaGetSymbolAddress(&pHh, g_Hh);
    cudaGetSymbolAddress(&pHf, g_Hf);
    cudaGetSymbolAddress(&pZ,  g_Z);
    cudaGetSymbolAddress(&pX2, g_X2);
    cudaGetSymbolAddress(&pON, g_out_norm);
    cudaGetSymbolAddress(&pDS, g_deg_src);
    cudaGetSymbolAddress(&pDD, g_deg_dst);
    cudaGetSymbolAddress(&pWt, g_Wt);
    __half* Ph = (__half*)pPh;
    float*  Rf = (float*)pRf;
    __half* Hh = (__half*)pHh;
    float*  Hf = (float*)pHf;
    float*  Z  = (float*)pZ;
    float*  X2 = (float*)pX2;
    float*  ONm = (float*)pON;
    __half* Wt0 = (__half*)pWt;
    __half* Wt1 = Wt0 + (size_t)256 * 128;

    cudaFuncSetAttribute(k_gemm_l1,  cudaFuncAttributeMaxDynamicSharedMemorySize, GEMM_SMEM);
    cudaFuncSetAttribute(k_gemm_l2h, cudaFuncAttributeMaxDynamicSharedMemorySize, GEMM_SMEM);

    int eb = (E + 255) / 256;
    int nb = (N + SCAN_CHUNK - 1) / SCAN_CHUNK;
    int gb = (N + 127) / 128;
    int wb = (N + 7) / 8;

    // launches: 1 memset, 2 memset, 3 wconv, 4 deg, 5 normchunk,
    //           6 gemm_l1 <- ncu skip-5 profile slot
    cudaMemsetAsync(pDS, 0, (size_t)N * sizeof(int), 0);
    cudaMemsetAsync(pDD, 0, (size_t)N * sizeof(int), 0);
    k_wconv<<<(2 * 256 * 128 + 255) / 256, 256>>>(W1, resW1, W2, resW2);
    k_deg<<<eb, 256>>>(src, dst, E);
    k_normchunk<<<nb, 256>>>(N);

    k_gemm_l1<<<gb, 512, GEMM_SMEM>>>(feats, Wt0, resb1, ONm, Ph, Rf, N);

    k_scan_bsums<<<1, 256>>>(nb, N);
    k_scan_final<<<nb, 256>>>(N);
    k_build<<<eb, 256>>>(src, dst, E);

    k_agg_h<<<wb, 256>>>(Ph, Rf, b1, N, Hh);                 // H1 fp16

    k_gemm_l2h<<<gb, 512, GEMM_SMEM>>>(Hh, Wt1, resb2, ONm, Ph, Rf, N);
    k_agg_f<<<wb, 256>>>(Ph, Rf, b2, N, Hf);                 // H2 fp32

    k_readout<<<(B + 7) / 8, 256>>>(Hf, gid, awW, awb, X2, ldx, N, B);

    dim3 gm1((B + MLPR - 1) / MLPR, (MH + 127) / 128);
    k_mlp<<<gm1, 128>>>(X2, ldx, orW1, orb1, org, orbeta, 1,
                        Z, MH, nullptr, 0, B, 256, MH);
    dim3 gm2((B + MLPR - 1) / MLPR, (T1 + 127) / 128);
    k_mlp<<<gm2, 128>>>(Z, MH, orW2, orb2, nullptr, nullptr, 0,
                        out, T1, X2 + 256, ldx, B, MH, T1);
    dim3 gm3((B + MLPR - 1) / MLPR, (MH + 127) / 128);
    k_mlp<<<gm3, 128>>>(X2, ldx, scW1, scb1, scg, scbeta, 1,
                        Z, MH, nullptr, 0, B, 256 + T1, MH);
    dim3 gm4((B + MLPR - 1) / MLPR, (T2 + 127) / 128);
    k_mlp<<<gm4, 128>>>(Z, MH, scW2, scb2, nullptr, nullptr, 0,
                        out_sc, T2, nullptr, 0, B, MH, T2);
}

// round 10
// speedup vs baseline: 1.3057x; 1.0128x over previous
#include <cuda_runtime.h>
#include <cuda_fp16.h>
#include <math.h>
#include <stdint.h>

// ---------------------------------------------------------------------------
// GCNJointPredictor, round 10:
//  - GEMM v4: 1024 threads / 32 warps (warp tile 32x32) -> 2x latency hiding
//    vs R9's 16 warps (occ 23%, no pipe saturated = latency-bound)
//  - merged scan kernel (offset computed inline per block)
//  - rest identical to R9 (670.4us best)
// ---------------------------------------------------------------------------

#define NMAX 100000
#define EMAX 3200000
#define BMAX 4096
#define HD   128
#define BN_INV 0.9999950000374997f
#define SCAN_CHUNK 1024

// ---- scratch (device globals) ----
__device__ __align__(16) __half g_Ph[(size_t)NMAX * HD];    // P (both layers)
__device__ __align__(16) float  g_Rf[(size_t)NMAX * HD];    // R (both layers)
__device__ __align__(16) __half g_Hh[(size_t)NMAX * HD];    // H1 fp16
__device__ __align__(16) float  g_Hf[(size_t)NMAX * HD];    // H2 fp32
__device__ __align__(16) float  g_Z[(size_t)BMAX * HD];
__device__ __align__(16) float  g_X2[(size_t)BMAX * 832];
__device__ __align__(16) __half g_Wt[2][256 * 128];         // [layer][n][k] fp16
__device__ int   g_deg_src[NMAX];
__device__ int   g_deg_dst[NMAX];
__device__ float g_out_norm[NMAX];
__device__ float g_in_norm[NMAX];
__device__ int   g_row_ptr[NMAX + 1];
__device__ int   g_cursor[NMAX];
__device__ int   g_esrc[EMAX];
__device__ int   g_bsum[256];

// ---------------------------------------------------------------------------
// one-shot weight transpose to fp16: Wt[n][k] = half(W[k][n])
// ---------------------------------------------------------------------------
__global__ void k_wconv(const float* __restrict__ W1, const float* __restrict__ rW1,
                        const float* __restrict__ W2, const float* __restrict__ rW2)
{
    int i = blockIdx.x * blockDim.x + threadIdx.x;
    if (i >= 2 * 256 * 128) return;
    int layer = i >> 15;
    int j = i & 32767;
    int n = j >> 7, k = j & 127;
    const float* src = (layer == 0) ? ((n < 128) ? W1 : rW1)
                                    : ((n < 128) ? W2 : rW2);
    g_Wt[layer][(size_t)n * 128 + k] = __float2half(src[(size_t)k * 128 + (n & 127)]);
}

__global__ void k_deg(const int* __restrict__ src, const int* __restrict__ dst, int E) {
    int e = blockIdx.x * blockDim.x + threadIdx.x;
    if (e < E) {
        atomicAdd(&g_deg_src[src[e]], 1);
        atomicAdd(&g_deg_dst[dst[e]], 1);
    }
}

// fused: norms + per-chunk sum of deg_dst
__global__ void k_normchunk(int Nn) {
    __shared__ int sdata[256];
    int base = blockIdx.x * SCAN_CHUNK;
    int s = 0;
    for (int i = threadIdx.x; i < SCAN_CHUNK; i += 256) {
        int idx = base + i;
        if (idx < Nn) {
            int ds = g_deg_src[idx], dd = g_deg_dst[idx];
            g_out_norm[idx] = rsqrtf((float)max(ds, 1));
            g_in_norm[idx]  = rsqrtf((float)max(dd, 1));
            s += dd;
        }
    }
    sdata[threadIdx.x] = s;
    __syncthreads();
    for (int off = 128; off > 0; off >>= 1) {
        if (threadIdx.x < off) sdata[threadIdx.x] += sdata[threadIdx.x + off];
        __syncthreads();
    }
    if (threadIdx.x == 0) g_bsum[blockIdx.x] = sdata[0];
}

// merged scan: per-block offset (sum of prior bsums) + local scan -> row_ptr/cursor
__global__ void k_scan2(int Nn) {
    __shared__ int s0[SCAN_CHUNK];
    __shared__ int s1[SCAN_CHUNK];
    __shared__ int rs[256];
    int t = threadIdx.x;
    int base = blockIdx.x * SCAN_CHUNK;

    int p = 0;
    for (int i = t; i < blockIdx.x; i += 256) p += g_bsum[i];
    rs[t] = p;
    __syncthreads();
    for (int o = 128; o > 0; o >>= 1) {
        if (t < o) rs[t] += rs[t + o];
        __syncthreads();
    }
    int off = rs[0];

    for (int i = t; i < SCAN_CHUNK; i += 256) {
        int idx = base + i;
        s0[i] = (idx < Nn) ? g_deg_dst[idx] : 0;
    }
    __syncthreads();
    int* a = s0; int* b = s1;
    for (int d = 1; d < SCAN_CHUNK; d <<= 1) {
        for (int i = t; i < SCAN_CHUNK; i += 256)
            b[i] = a[i] + (i >= d ? a[i - d] : 0);
        __syncthreads();
        int* tmp = a; a = b; b = tmp;
    }
    for (int i = t; i < SCAN_CHUNK; i += 256) {
        int idx = base + i;
        if (idx < Nn) {
            int ex = off + (i > 0 ? a[i - 1] : 0);
            g_row_ptr[idx] = ex;
            g_cursor[idx]  = ex;
        }
    }
    if (blockIdx.x == gridDim.x - 1 && t == 0)
        g_row_ptr[Nn] = off + a[SCAN_CHUNK - 1];
}

__global__ void k_build(const int* __restrict__ src, const int* __restrict__ dst, int E) {
    int e = blockIdx.x * blockDim.x + threadIdx.x;
    if (e < E) {
        int p = atomicAdd(&g_cursor[dst[e]], 1);
        g_esrc[p] = src[e];
    }
}

// ---------------------------------------------------------------------------
// fused fp16 tensor-core GEMM core (one barrier, W+X smem resident)
// block 128 rows x 256 cols, 1024 thr (32 warps, 4M x 8N), warp tile 32x32
// Epilogue: cols [0,128) -> Pout fp16 * rowscale; [128,256) -> RoutF relu fp32
// ---------------------------------------------------------------------------
#define WP 136
#define GEMM_SMEM ((256 * WP + 128 * WP) * 2)   // 104448 bytes

#define MMA_F16(c, a0, a1, a2, a3, b0, b1)                                   \
    asm volatile(                                                            \
        "mma.sync.aligned.m16n8k16.row.col.f32.f16.f16.f32 "                 \
        "{%0,%1,%2,%3}, {%4,%5,%6,%7}, {%8,%9}, {%0,%1,%2,%3};"              \
        : "+f"((c)[0]), "+f"((c)[1]), "+f"((c)[2]), "+f"((c)[3])             \
        : "r"(a0), "r"(a1), "r"(a2), "r"(a3), "r"(b0), "r"(b1))

#define GEMM_MAIN_AND_EPI()                                                  \
    float acc[2][4][4];                                                      \
    _Pragma("unroll")                                                        \
    for (int mt = 0; mt < 2; mt++)                                           \
        _Pragma("unroll")                                                    \
        for (int nt = 0; nt < 4; nt++)                                       \
            _Pragma("unroll")                                                \
            for (int q = 0; q < 4; q++) acc[mt][nt][q] = 0.f;                \
    _Pragma("unroll")                                                        \
    for (int c = 0; c < 8; c++) {                                            \
        int kk = c * 16;                                                     \
        uint32_t a[2][4];                                                    \
        _Pragma("unroll")                                                    \
        for (int mt = 0; mt < 2; mt++) {                                     \
            int r = wm * 32 + mt * 16 + gq;                                  \
            a[mt][0] = *reinterpret_cast<uint32_t*>(&Xs[r * WP + kk + tg * 2]);          \
            a[mt][1] = *reinterpret_cast<uint32_t*>(&Xs[(r + 8) * WP + kk + tg * 2]);    \
            a[mt][2] = *reinterpret_cast<uint32_t*>(&Xs[r * WP + kk + 8 + tg * 2]);      \
            a[mt][3] = *reinterpret_cast<uint32_t*>(&Xs[(r + 8) * WP + kk + 8 + tg * 2]);\
        }                                                                    \
        _Pragma("unroll")                                                    \
        for (int nt = 0; nt < 4; nt++) {                                     \
            int nb = wn * 32 + nt * 8 + gq;                                  \
            uint32_t b0 = *reinterpret_cast<uint32_t*>(&Ws[nb * WP + kk + tg * 2]);      \
            uint32_t b1 = *reinterpret_cast<uint32_t*>(&Ws[nb * WP + kk + 8 + tg * 2]);  \
            _Pragma("unroll")                                                \
            for (int mt = 0; mt < 2; mt++)                                   \
                MMA_F16(acc[mt][nt], a[mt][0], a[mt][1], a[mt][2], a[mt][3], b0, b1);    \
        }                                                                    \
    }                                                                        \
    _Pragma("unroll")                                                        \
    for (int mt = 0; mt < 2; mt++) {                                         \
        int r0 = row0 + wm * 32 + mt * 16 + gq;                              \
        int r1 = r0 + 8;                                                     \
        if (wn < 4) {                                                        \
            float s0 = (r0 < M) ? rowscale[r0] : 0.f;                        \
            float s1 = (r1 < M) ? rowscale[r1] : 0.f;                        \
            _Pragma("unroll")                                                \
            for (int nt = 0; nt < 4; nt++) {                                 \
                int c = wn * 32 + nt * 8 + tg * 2;                           \
                float* a = acc[mt][nt];                                      \
                if (r0 < M)                                                  \
                    *reinterpret_cast<__half2*>(&Pout[(size_t)r0 * 128 + c]) =           \
                        __floats2half2_rn(a[0] * s0, a[1] * s0);             \
                if (r1 < M)                                                  \
                    *reinterpret_cast<__half2*>(&Pout[(size_t)r1 * 128 + c]) =           \
                        __floats2half2_rn(a[2] * s1, a[3] * s1);             \
            }                                                                \
        } else {                                                             \
            _Pragma("unroll")                                                \
            for (int nt = 0; nt < 4; nt++) {                                 \
                int c = (wn - 4) * 32 + nt * 8 + tg * 2;                     \
                float* a = acc[mt][nt];                                      \
                float b0 = resb[c], b1 = resb[c + 1];                        \
                if (r0 < M)                                                  \
                    *reinterpret_cast<float2*>(&RoutF[(size_t)r0 * 128 + c]) =           \
                        make_float2(fmaxf(a[0] + b0, 0.f), fmaxf(a[1] + b1, 0.f));       \
                if (r1 < M)                                                  \
                    *reinterpret_cast<float2*>(&RoutF[(size_t)r1 * 128 + c]) =           \
                        make_float2(fmaxf(a[2] + b0, 0.f), fmaxf(a[3] + b1, 0.f));       \
            }                                                                \
        }                                                                    \
    }

// ---- layer 1: X from fp32 global ----
__global__ __launch_bounds__(1024) void k_gemm_l1(
    const float* __restrict__ X, const __half* __restrict__ Wt,
    const float* __restrict__ resb, const float* __restrict__ rowscale,
    __half* __restrict__ Pout, float* __restrict__ RoutF, int M)
{
    extern __shared__ __half sm[];
    __half* Ws = sm;
    __half* Xs = sm + 256 * WP;
    int tid = threadIdx.x;
    int lane = tid & 31, wid = tid >> 5;
    int wm = wid & 3, wn = wid >> 2;        // 4 warps M x 8 warps N
    int gq = lane >> 2, tg = lane & 3;
    int row0 = blockIdx.x * 128;

    // W: 4096 uint4 over 1024 thr
#pragma unroll
    for (int i = tid; i < 4096; i += 1024) {
        int n = i >> 4, kb = (i & 15) * 8;
        *reinterpret_cast<uint4*>(&Ws[n * WP + kb]) =
            *reinterpret_cast<const uint4*>(&Wt[(size_t)n * 128 + kb]);
    }
    // X: each thread 1 row x 16 cols (4 float4)
    {
        int xr = tid >> 3, xc0 = (tid & 7) * 16;
        int gr = row0 + xr;
        bool rowok = (gr < M);
        const float4* xrow = reinterpret_cast<const float4*>(&X[(size_t)gr * 128 + xc0]);
#pragma unroll
        for (int j = 0; j < 4; j++) {
            float4 v = make_float4(0.f, 0.f, 0.f, 0.f);
            if (rowok) v = xrow[j];
            __half2 h01 = __floats2half2_rn(v.x, v.y);
            __half2 h23 = __floats2half2_rn(v.z, v.w);
            uint2 u;
            u.x = *reinterpret_cast<uint32_t*>(&h01);
            u.y = *reinterpret_cast<uint32_t*>(&h23);
            *reinterpret_cast<uint2*>(&Xs[xr * WP + xc0 + j * 4]) = u;
        }
    }
    __syncthreads();
    GEMM_MAIN_AND_EPI()
}

// ---- layer 2: X from fp16 global (H1) ----
__global__ __launch_bounds__(1024) void k_gemm_l2h(
    const __half* __restrict__ Xh, const __half* __restrict__ Wt,
    const float* __restrict__ resb, const float* __restrict__ rowscale,
    __half* __restrict__ Pout, float* __restrict__ RoutF, int M)
{
    extern __shared__ __half sm[];
    __half* Ws = sm;
    __half* Xs = sm + 256 * WP;
    int tid = threadIdx.x;
    int lane = tid & 31, wid = tid >> 5;
    int wm = wid & 3, wn = wid >> 2;
    int gq = lane >> 2, tg = lane & 3;
    int row0 = blockIdx.x * 128;

#pragma unroll
    for (int i = tid; i < 4096; i += 1024) {
        int n = i >> 4, kb = (i & 15) * 8;
        *reinterpret_cast<uint4*>(&Ws[n * WP + kb]) =
            *reinterpret_cast<const uint4*>(&Wt[(size_t)n * 128 + kb]);
    }
    {
        // each thread 1 row x 16 halves (2 uint4)
        int xr = tid >> 3, xc0 = (tid & 7) * 16;
        int gr = row0 + xr;
        bool rowok = (gr < M);
        const uint4* xrow = reinterpret_cast<const uint4*>(&Xh[(size_t)gr * 128 + xc0]);
#pragma unroll
        for (int j = 0; j < 2; j++) {
            uint4 v = make_uint4(0u, 0u, 0u, 0u);
            if (rowok) v = xrow[j];
            *reinterpret_cast<uint4*>(&Xs[xr * WP + xc0 + j * 8]) = v;
        }
    }
    __syncthreads();
    GEMM_MAIN_AND_EPI()
}

// ---------------------------------------------------------------------------
// aggregation: warp per node, fp16 P rows, 4-edge unroll, fp32 accumulate
// ---------------------------------------------------------------------------
__device__ __forceinline__ float4 agg_node(const __half* __restrict__ P,
                                           const float* __restrict__ R,
                                           float4 b, int w, int lane)
{
    int e0 = g_row_ptr[w], e1 = g_row_ptr[w + 1];
    const uint2* P2 = reinterpret_cast<const uint2*>(P);
    float4 acc = make_float4(0.f, 0.f, 0.f, 0.f);
    int e = e0;
#define ACCV(v) { \
    float2 p0 = __half22float2(*reinterpret_cast<__half2*>(&(v).x)); \
    float2 p1 = __half22float2(*reinterpret_cast<__half2*>(&(v).y)); \
    acc.x += p0.x; acc.y += p0.y; acc.z += p1.x; acc.w += p1.y; }
    for (; e + 3 < e1; e += 4) {
        int u0 = g_esrc[e],     u1 = g_esrc[e + 1];
        int u2 = g_esrc[e + 2], u3 = g_esrc[e + 3];
        uint2 v0 = P2[(size_t)u0 * 32 + lane];
        uint2 v1 = P2[(size_t)u1 * 32 + lane];
        uint2 v2 = P2[(size_t)u2 * 32 + lane];
        uint2 v3 = P2[(size_t)u3 * 32 + lane];
        ACCV(v0); ACCV(v1); ACCV(v2); ACCV(v3);
    }
    for (; e < e1; e++) {
        int u = g_esrc[e];
        uint2 v = P2[(size_t)u * 32 + lane];
        ACCV(v);
    }
#undef ACCV
    float inn = g_in_norm[w];
    float4 r = reinterpret_cast<const float4*>(R)[(size_t)w * 32 + lane];
    float4 o;
    o.x = fmaxf(fmaf(acc.x, inn, b.x), 0.f) + r.x;
    o.y = fmaxf(fmaf(acc.y, inn, b.y), 0.f) + r.y;
    o.z = fmaxf(fmaf(acc.z, inn, b.z), 0.f) + r.z;
    o.w = fmaxf(fmaf(acc.w, inn, b.w), 0.f) + r.w;
    return o;
}

__global__ void k_agg_h(const __half* __restrict__ P, const float* __restrict__ R,
                        const float* __restrict__ bias, int Nn, __half* __restrict__ out)
{
    int w = (int)((blockIdx.x * (size_t)blockDim.x + threadIdx.x) >> 5);
    int lane = threadIdx.x & 31;
    if (w >= Nn) return;
    float4 b = reinterpret_cast<const float4*>(bias)[lane];
    float4 o = agg_node(P, R, b, w, lane);
    __half2 h01 = __floats2half2_rn(o.x, o.y);
    __half2 h23 = __floats2half2_rn(o.z, o.w);
    uint2 u;
    u.x = *reinterpret_cast<uint32_t*>(&h01);
    u.y = *reinterpret_cast<uint32_t*>(&h23);
    reinterpret_cast<uint2*>(out)[(size_t)w * 32 + lane] = u;
}

__global__ void k_agg_f(const __half* __restrict__ P, const float* __restrict__ R,
                        const float* __restrict__ bias, int Nn, float* __restrict__ out)
{
    int w = (int)((blockIdx.x * (size_t)blockDim.x + threadIdx.x) >> 5);
    int lane = threadIdx.x & 31;
    if (w >= Nn) return;
    float4 b = reinterpret_cast<const float4*>(bias)[lane];
    float4 o = agg_node(P, R, b, w, lane);
    reinterpret_cast<float4*>(out)[(size_t)w * 32 + lane] = o;
}

// ---------------------------------------------------------------------------
// readout: warp per graph, binary search on sorted gid, no atomics
// ---------------------------------------------------------------------------
__global__ void k_readout(const float* __restrict__ H, const int* __restrict__ gid,
                          const float* __restrict__ awW, const float* __restrict__ awb,
                          float* __restrict__ X2, int ldx, int Nn, int Bg)
{
    int g = (int)((blockIdx.x * (size_t)blockDim.x + threadIdx.x) >> 5);
    int lane = threadIdx.x & 31;
    if (g >= Bg) return;
    int lo = 0, hi = Nn;
    while (lo < hi) { int mid = (lo + hi) >> 1; if (gid[mid] < g) lo = mid + 1; else hi = mid; }
    int lo2 = lo, hi2 = Nn;
    while (lo2 < hi2) { int mid = (lo2 + hi2) >> 1; if (gid[mid] < g + 1) lo2 = mid + 1; else hi2 = mid; }

    float4 a = reinterpret_cast<const float4*>(awW)[lane];
    float ab = awb[0];
    float4 s  = make_float4(0.f, 0.f, 0.f, 0.f);
    float4 mx = make_float4(0.f, 0.f, 0.f, 0.f);   // h >= 0
    const float4* H4 = reinterpret_cast<const float4*>(H);
    for (int i = lo; i < lo2; i++) {
        float4 h = H4[(size_t)i * 32 + lane];
        float d = h.x * a.x + h.y * a.y + h.z * a.z + h.w * a.w;
#pragma unroll
        for (int o = 16; o; o >>= 1) d += __shfl_xor_sync(0xffffffffu, d, o);
        float aw = 1.f / (1.f + expf(-(d + ab)));
        s.x += aw * h.x; s.y += aw * h.y; s.z += aw * h.z; s.w += aw * h.w;
        mx.x = fmaxf(mx.x, h.x); mx.y = fmaxf(mx.y, h.y);
        mx.z = fmaxf(mx.z, h.z); mx.w = fmaxf(mx.w, h.w);
    }
    *reinterpret_cast<float4*>(&X2[(size_t)g * ldx + lane * 4]) = s;
    *reinterpret_cast<float4*>(&X2[(size_t)g * ldx + 128 + lane * 4]) = mx;
}

// ---------------------------------------------------------------------------
// MLP GEMM (fp32 SIMT, k-blocked float4 inner loop, 16 rows/block)
// ---------------------------------------------------------------------------
#define MLPR 16
__global__ __launch_bounds__(128) void k_mlp(
    const float* __restrict__ A, int lda,
    const float* __restrict__ W, const float* __restrict__ bias,
    const float* __restrict__ gamma, const float* __restrict__ beta, int mode,
    float* __restrict__ out1, int ldo1, float* __restrict__ out2, int ldo2,
    int M, int K, int Nc)
{
    __shared__ float As[MLPR][36];
    __shared__ float Ws[32][128];
    int row0 = blockIdx.x * MLPR;
    int n0 = blockIdx.y * 128;
    int col = threadIdx.x;
    float acc[MLPR];
#pragma unroll
    for (int r = 0; r < MLPR; r++) acc[r] = 0.f;

    for (int k0 = 0; k0 < K; k0 += 32) {
        for (int i = threadIdx.x; i < MLPR * 32; i += 128) {
            int r = i >> 5, k = i & 31;
            int gk = k0 + k, gr = row0 + r;
            As[r][k] = (gk < K && gr < M) ? A[(size_t)gr * lda + gk] : 0.f;
        }
        for (int i = threadIdx.x; i < 4096; i += 128) {
            int kr = i >> 7, c = i & 127;
            int gk = k0 + kr, gc = n0 + c;
            Ws[kr][c] = (gk < K && gc < Nc) ? W[(size_t)gk * Nc + gc] : 0.f;
        }
        __syncthreads();
#pragma unroll
        for (int kb = 0; kb < 8; kb++) {
            float w0 = Ws[kb * 4 + 0][col];
            float w1 = Ws[kb * 4 + 1][col];
            float w2 = Ws[kb * 4 + 2][col];
            float w3 = Ws[kb * 4 + 3][col];
#pragma unroll
            for (int r = 0; r < MLPR; r++) {
                float4 a = *reinterpret_cast<const float4*>(&As[r][kb * 4]);
                acc[r] = fmaf(a.x, w0, acc[r]);
                acc[r] = fmaf(a.y, w1, acc[r]);
                acc[r] = fmaf(a.z, w2, acc[r]);
                acc[r] = fmaf(a.w, w3, acc[r]);
            }
        }
        __syncthreads();
    }
    int gc = n0 + col;
    if (gc >= Nc) return;
    float bv = bias ? bias[gc] : 0.f;
    float gam = (mode == 1) ? gamma[gc] * BN_INV : 0.f;
    float bet = (mode == 1) ? beta[gc] : 0.f;
#pragma unroll
    for (int r = 0; r < MLPR; r++) {
        int gr = row0 + r;
        if (gr >= M) break;
        float v = acc[r] + bv;
        if (mode == 1) v = fmaxf(v, 0.f) * gam + bet;
        out1[(size_t)gr * ldo1 + gc] = v;
        if (out2) out2[(size_t)gr * ldo2 + gc] = v;
    }
}

// ---------------------------------------------------------------------------
// host
// ---------------------------------------------------------------------------
extern "C" void kernel_launch(void* const* d_in, const int* in_sizes, int n_in,
                              void* d_out, int out_size)
{
    const float* feats  = (const float*)d_in[0];
    const int*   src    = (const int*)  d_in[1];
    const int*   dst    = (const int*)  d_in[2];
    const int*   gid    = (const int*)  d_in[3];
    const float* W1     = (const float*)d_in[4];
    const float* b1     = (const float*)d_in[5];
    const float* resW1  = (const float*)d_in[6];
    const float* resb1  = (const float*)d_in[7];
    const float* W2     = (const float*)d_in[8];
    const float* b2     = (const float*)d_in[9];
    const float* resW2  = (const float*)d_in[10];
    const float* resb2  = (const float*)d_in[11];
    const float* awW    = (const float*)d_in[12];
    const float* awb    = (const float*)d_in[13];
    const float* orW1   = (const float*)d_in[14];
    const float* orb1   = (const float*)d_in[15];
    const float* org    = (const float*)d_in[16];
    const float* orbeta = (const float*)d_in[17];
    const float* orW2   = (const float*)d_in[18];
    const float* orb2   = (const float*)d_in[19];
    const float* scW1   = (const float*)d_in[20];
    const float* scb1   = (const float*)d_in[21];
    const float* scg    = (const float*)d_in[22];
    const float* scbeta = (const float*)d_in[23];
    const float* scW2   = (const float*)d_in[24];
    const float* scb2   = (const float*)d_in[25];

    int N  = in_sizes[0] / HD;
    int E  = in_sizes[1];
    int T1 = in_sizes[19];
    int T2 = in_sizes[25];
    int MH = in_sizes[15];
    int B  = out_size / (T1 + T2);
    int ldx = 832;

    float* out    = (float*)d_out;
    float* out_sc = out + (size_t)B * T1;

    void *pPh, *pRf, *pHh, *pHf, *pZ, *pX2, *pON, *pDS, *pDD, *pWt;
    cudaGetSymbolAddress(&pPh, g_Ph);
    cudaGetSymbolAddress(&pRf, g_Rf);
    cudaGetSymbolAddress(&pHh, g_Hh);
    cudaGetSymbolAddress(&pHf, g_Hf);
    cudaGetSymbolAddress(&pZ,  g_Z);
    cudaGetSymbolAddress(&pX2, g_X2);
    cudaGetSymbolAddress(&pON, g_out_norm);
    cudaGetSymbolAddress(&pDS, g_deg_src);
    cudaGetSymbolAddress(&pDD, g_deg_dst);
    cudaGetSymbolAddress(&pWt, g_Wt);
    __half* Ph = (__half*)pPh;
    float*  Rf = (float*)pRf;
    __half* Hh = (__half*)pHh;
    float*  Hf = (float*)pHf;
    float*  Z  = (float*)pZ;
    float*  X2 = (float*)pX2;
    float*  ONm = (float*)pON;
    __half* Wt0 = (__half*)pWt;
    __half* Wt1 = Wt0 + (size_t)256 * 128;

    cudaFuncSetAttribute(k_gemm_l1,  cudaFuncAttributeMaxDynamicSharedMemorySize, GEMM_SMEM);
    cudaFuncSetAttribute(k_gemm_l2h, cudaFuncAttributeMaxDynamicSharedMemorySize, GEMM_SMEM);

    int eb = (E + 255) / 256;
    int nb = (N + SCAN_CHUNK - 1) / SCAN_CHUNK;
    int gb = (N + 127) / 128;
    int wb = (N + 7) / 8;

    // launches: 1 memset, 2 memset, 3 wconv, 4 deg, 5 normchunk,
    //           6 gemm_l1 <- ncu skip-5 profile slot
    cudaMemsetAsync(pDS, 0, (size_t)N * sizeof(int), 0);
    cudaMemsetAsync(pDD, 0, (size_t)N * sizeof(int), 0);
    k_wconv<<<(2 * 256 * 128 + 255) / 256, 256>>>(W1, resW1, W2, resW2);
    k_deg<<<eb, 256>>>(src, dst, E);
    k_normchunk<<<nb, 256>>>(N);

    k_gemm_l1<<<gb, 1024, GEMM_SMEM>>>(feats, Wt0, resb1, ONm, Ph, Rf, N);

    k_scan2<<<nb, 256>>>(N);
    k_build<<<eb, 256>>>(src, dst, E);

    k_agg_h<<<wb, 256>>>(Ph, Rf, b1, N, Hh);                 // H1 fp16

    k_gemm_l2h<<<gb, 1024, GEMM_SMEM>>>(Hh, Wt1, resb2, ONm, Ph, Rf, N);
    k_agg_f<<<wb, 256>>>(Ph, Rf, b2, N, Hf);                 // H2 fp32

    k_readout<<<(B + 7) / 8, 256>>>(Hf, gid, awW, awb, X2, ldx, N, B);

    dim3 gm1((B + MLPR - 1) / MLPR, (MH + 127) / 128);
    k_mlp<<<gm1, 128>>>(X2, ldx, orW1, orb1, org, orbeta, 1,
                        Z, MH, nullptr, 0, B, 256, MH);
    dim3 gm2((B + MLPR - 1) / MLPR, (T1 + 127) / 128);
    k_mlp<<<gm2, 128>>>(Z, MH, orW2, orb2, nullptr, nullptr, 0,
                        out, T1, X2 + 256, ldx, B, MH, T1);
    dim3 gm3((B + MLPR - 1) / MLPR, (MH + 127) / 128);
    k_mlp<<<gm3, 128>>>(X2, ldx, scW1, scb1, scg, scbeta, 1,
                        Z, MH, nullptr, 0, B, 256 + T1, MH);
    dim3 gm4((B + MLPR - 1) / MLPR, (T2 + 127) / 128);
    k_mlp<<<gm4, 128>>>(Z, MH, scW2, scb2, nullptr, nullptr, 0,
                        out_sc, T2, nullptr, 0, B, MH, T2);
}

// round 11
// speedup vs baseline: 1.5571x; 1.1926x over previous
#include <cuda_runtime.h>
#include <cuda_fp16.h>
#include <math.h>
#include <stdint.h>

// ---------------------------------------------------------------------------
// GCNJointPredictor, round 11:
//  - fused MLP head: one kernel, 8 graphs/block, all intermediates in smem,
//    weights streamed from L2 (replaces 4 k_mlp launches + Z/X2 roundtrips)
//  - k_zero replaces 2 memsets (one less launch)
//  - GEMM/agg/readout identical to R10 (661.9us best)
// ---------------------------------------------------------------------------

#define NMAX 100000
#define EMAX 3200000
#define BMAX 4096
#define HD   128
#define BN_INV 0.9999950000374997f
#define SCAN_CHUNK 1024

// ---- scratch (device globals) ----
__device__ __align__(16) __half g_Ph[(size_t)NMAX * HD];    // P (both layers)
__device__ __align__(16) float  g_Rf[(size_t)NMAX * HD];    // R (both layers)
__device__ __align__(16) __half g_Hh[(size_t)NMAX * HD];    // H1 fp16
__device__ __align__(16) float  g_Hf[(size_t)NMAX * HD];    // H2 fp32
__device__ __align__(16) float  g_X2[(size_t)BMAX * 256];   // [hsum|hmax]
__device__ __align__(16) __half g_Wt[2][256 * 128];         // [layer][n][k] fp16
__device__ int   g_deg_src[NMAX];
__device__ int   g_deg_dst[NMAX];
__device__ float g_out_norm[NMAX];
__device__ float g_in_norm[NMAX];
__device__ int   g_row_ptr[NMAX + 1];
__device__ int   g_cursor[NMAX];
__device__ int   g_esrc[EMAX];
__device__ int   g_bsum[256];

// ---------------------------------------------------------------------------
__global__ void k_zero(int Nn) {
    int i = blockIdx.x * blockDim.x + threadIdx.x;
    if (i < Nn) { g_deg_src[i] = 0; g_deg_dst[i] = 0; }
}

// one-shot weight transpose to fp16: Wt[n][k] = half(W[k][n])
__global__ void k_wconv(const float* __restrict__ W1, const float* __restrict__ rW1,
                        const float* __restrict__ W2, const float* __restrict__ rW2)
{
    int i = blockIdx.x * blockDim.x + threadIdx.x;
    if (i >= 2 * 256 * 128) return;
    int layer = i >> 15;
    int j = i & 32767;
    int n = j >> 7, k = j & 127;
    const float* src = (layer == 0) ? ((n < 128) ? W1 : rW1)
                                    : ((n < 128) ? W2 : rW2);
    g_Wt[layer][(size_t)n * 128 + k] = __float2half(src[(size_t)k * 128 + (n & 127)]);
}

__global__ void k_deg(const int* __restrict__ src, const int* __restrict__ dst, int E) {
    int e = blockIdx.x * blockDim.x + threadIdx.x;
    if (e < E) {
        atomicAdd(&g_deg_src[src[e]], 1);
        atomicAdd(&g_deg_dst[dst[e]], 1);
    }
}

// fused: norms + per-chunk sum of deg_dst
__global__ void k_normchunk(int Nn) {
    __shared__ int sdata[256];
    int base = blockIdx.x * SCAN_CHUNK;
    int s = 0;
    for (int i = threadIdx.x; i < SCAN_CHUNK; i += 256) {
        int idx = base + i;
        if (idx < Nn) {
            int ds = g_deg_src[idx], dd = g_deg_dst[idx];
            g_out_norm[idx] = rsqrtf((float)max(ds, 1));
            g_in_norm[idx]  = rsqrtf((float)max(dd, 1));
            s += dd;
        }
    }
    sdata[threadIdx.x] = s;
    __syncthreads();
    for (int off = 128; off > 0; off >>= 1) {
        if (threadIdx.x < off) sdata[threadIdx.x] += sdata[threadIdx.x + off];
        __syncthreads();
    }
    if (threadIdx.x == 0) g_bsum[blockIdx.x] = sdata[0];
}

// merged scan: per-block offset + local scan -> row_ptr/cursor
__global__ void k_scan2(int Nn) {
    __shared__ int s0[SCAN_CHUNK];
    __shared__ int s1[SCAN_CHUNK];
    __shared__ int rs[256];
    int t = threadIdx.x;
    int base = blockIdx.x * SCAN_CHUNK;

    int p = 0;
    for (int i = t; i < blockIdx.x; i += 256) p += g_bsum[i];
    rs[t] = p;
    __syncthreads();
    for (int o = 128; o > 0; o >>= 1) {
        if (t < o) rs[t] += rs[t + o];
        __syncthreads();
    }
    int off = rs[0];

    for (int i = t; i < SCAN_CHUNK; i += 256) {
        int idx = base + i;
        s0[i] = (idx < Nn) ? g_deg_dst[idx] : 0;
    }
    __syncthreads();
    int* a = s0; int* b = s1;
    for (int d = 1; d < SCAN_CHUNK; d <<= 1) {
        for (int i = t; i < SCAN_CHUNK; i += 256)
            b[i] = a[i] + (i >= d ? a[i - d] : 0);
        __syncthreads();
        int* tmp = a; a = b; b = tmp;
    }
    for (int i = t; i < SCAN_CHUNK; i += 256) {
        int idx = base + i;
        if (idx < Nn) {
            int ex = off + (i > 0 ? a[i - 1] : 0);
            g_row_ptr[idx] = ex;
            g_cursor[idx]  = ex;
        }
    }
    if (blockIdx.x == gridDim.x - 1 && t == 0)
        g_row_ptr[Nn] = off + a[SCAN_CHUNK - 1];
}

__global__ void k_build(const int* __restrict__ src, const int* __restrict__ dst, int E) {
    int e = blockIdx.x * blockDim.x + threadIdx.x;
    if (e < E) {
        int p = atomicAdd(&g_cursor[dst[e]], 1);
        g_esrc[p] = src[e];
    }
}

// ---------------------------------------------------------------------------
// fused fp16 tensor-core GEMM core (one barrier, W+X smem resident)
// block 128 rows x 256 cols, 1024 thr (32 warps, 4M x 8N), warp tile 32x32
// ---------------------------------------------------------------------------
#define WP 136
#define GEMM_SMEM ((256 * WP + 128 * WP) * 2)   // 104448 bytes

#define MMA_F16(c, a0, a1, a2, a3, b0, b1)                                   \
    asm volatile(                                                            \
        "mma.sync.aligned.m16n8k16.row.col.f32.f16.f16.f32 "                 \
        "{%0,%1,%2,%3}, {%4,%5,%6,%7}, {%8,%9}, {%0,%1,%2,%3};"              \
        : "+f"((c)[0]), "+f"((c)[1]), "+f"((c)[2]), "+f"((c)[3])             \
        : "r"(a0), "r"(a1), "r"(a2), "r"(a3), "r"(b0), "r"(b1))

#define GEMM_MAIN_AND_EPI()                                                  \
    float acc[2][4][4];                                                      \
    _Pragma("unroll")                                                        \
    for (int mt = 0; mt < 2; mt++)                                           \
        _Pragma("unroll")                                                    \
        for (int nt = 0; nt < 4; nt++)                                       \
            _Pragma("unroll")                                                \
            for (int q = 0; q < 4; q++) acc[mt][nt][q] = 0.f;                \
    _Pragma("unroll")                                                        \
    for (int c = 0; c < 8; c++) {                                            \
        int kk = c * 16;                                                     \
        uint32_t a[2][4];                                                    \
        _Pragma("unroll")                                                    \
        for (int mt = 0; mt < 2; mt++) {                                     \
            int r = wm * 32 + mt * 16 + gq;                                  \
            a[mt][0] = *reinterpret_cast<uint32_t*>(&Xs[r * WP + kk + tg * 2]);          \
            a[mt][1] = *reinterpret_cast<uint32_t*>(&Xs[(r + 8) * WP + kk + tg * 2]);    \
            a[mt][2] = *reinterpret_cast<uint32_t*>(&Xs[r * WP + kk + 8 + tg * 2]);      \
            a[mt][3] = *reinterpret_cast<uint32_t*>(&Xs[(r + 8) * WP + kk + 8 + tg * 2]);\
        }                                                                    \
        _Pragma("unroll")                                                    \
        for (int nt = 0; nt < 4; nt++) {                                     \
            int nb = wn * 32 + nt * 8 + gq;                                  \
            uint32_t b0 = *reinterpret_cast<uint32_t*>(&Ws[nb * WP + kk + tg * 2]);      \
            uint32_t b1 = *reinterpret_cast<uint32_t*>(&Ws[nb * WP + kk + 8 + tg * 2]);  \
            _Pragma("unroll")                                                \
            for (int mt = 0; mt < 2; mt++)                                   \
                MMA_F16(acc[mt][nt], a[mt][0], a[mt][1], a[mt][2], a[mt][3], b0, b1);    \
        }                                                                    \
    }                                                                        \
    _Pragma("unroll")                                                        \
    for (int mt = 0; mt < 2; mt++) {                                         \
        int r0 = row0 + wm * 32 + mt * 16 + gq;                              \
        int r1 = r0 + 8;                                                     \
        if (wn < 4) {                                                        \
            float s0 = (r0 < M) ? rowscale[r0] : 0.f;                        \
            float s1 = (r1 < M) ? rowscale[r1] : 0.f;                        \
            _Pragma("unroll")                                                \
            for (int nt = 0; nt < 4; nt++) {                                 \
                int c = wn * 32 + nt * 8 + tg * 2;                           \
                float* a = acc[mt][nt];                                      \
                if (r0 < M)                                                  \
                    *reinterpret_cast<__half2*>(&Pout[(size_t)r0 * 128 + c]) =           \
                        __floats2half2_rn(a[0] * s0, a[1] * s0);             \
                if (r1 < M)                                                  \
                    *reinterpret_cast<__half2*>(&Pout[(size_t)r1 * 128 + c]) =           \
                        __floats2half2_rn(a[2] * s1, a[3] * s1);             \
            }                                                                \
        } else {                                                             \
            _Pragma("unroll")                                                \
            for (int nt = 0; nt < 4; nt++) {                                 \
                int c = (wn - 4) * 32 + nt * 8 + tg * 2;                     \
                float* a = acc[mt][nt];                                      \
                float b0 = resb[c], b1 = resb[c + 1];                        \
                if (r0 < M)                                                  \
                    *reinterpret_cast<float2*>(&RoutF[(size_t)r0 * 128 + c]) =           \
                        make_float2(fmaxf(a[0] + b0, 0.f), fmaxf(a[1] + b1, 0.f));       \
                if (r1 < M)                                                  \
                    *reinterpret_cast<float2*>(&RoutF[(size_t)r1 * 128 + c]) =           \
                        make_float2(fmaxf(a[2] + b0, 0.f), fmaxf(a[3] + b1, 0.f));       \
            }                                                                \
        }                                                                    \
    }

// ---- layer 1: X from fp32 global ----
__global__ __launch_bounds__(1024) void k_gemm_l1(
    const float* __restrict__ X, const __half* __restrict__ Wt,
    const float* __restrict__ resb, const float* __restrict__ rowscale,
    __half* __restrict__ Pout, float* __restrict__ RoutF, int M)
{
    extern __shared__ __half sm[];
    __half* Ws = sm;
    __half* Xs = sm + 256 * WP;
    int tid = threadIdx.x;
    int lane = tid & 31, wid = tid >> 5;
    int wm = wid & 3, wn = wid >> 2;
    int gq = lane >> 2, tg = lane & 3;
    int row0 = blockIdx.x * 128;

#pragma unroll
    for (int i = tid; i < 4096; i += 1024) {
        int n = i >> 4, kb = (i & 15) * 8;
        *reinterpret_cast<uint4*>(&Ws[n * WP + kb]) =
            *reinterpret_cast<const uint4*>(&Wt[(size_t)n * 128 + kb]);
    }
    {
        int xr = tid >> 3, xc0 = (tid & 7) * 16;
        int gr = row0 + xr;
        bool rowok = (gr < M);
        const float4* xrow = reinterpret_cast<const float4*>(&X[(size_t)gr * 128 + xc0]);
#pragma unroll
        for (int j = 0; j < 4; j++) {
            float4 v = make_float4(0.f, 0.f, 0.f, 0.f);
            if (rowok) v = xrow[j];
            __half2 h01 = __floats2half2_rn(v.x, v.y);
            __half2 h23 = __floats2half2_rn(v.z, v.w);
            uint2 u;
            u.x = *reinterpret_cast<uint32_t*>(&h01);
            u.y = *reinterpret_cast<uint32_t*>(&h23);
            *reinterpret_cast<uint2*>(&Xs[xr * WP + xc0 + j * 4]) = u;
        }
    }
    __syncthreads();
    GEMM_MAIN_AND_EPI()
}

// ---- layer 2: X from fp16 global (H1) ----
__global__ __launch_bounds__(1024) void k_gemm_l2h(
    const __half* __restrict__ Xh, const __half* __restrict__ Wt,
    const float* __restrict__ resb, const float* __restrict__ rowscale,
    __half* __restrict__ Pout, float* __restrict__ RoutF, int M)
{
    extern __shared__ __half sm[];
    __half* Ws = sm;
    __half* Xs = sm + 256 * WP;
    int tid = threadIdx.x;
    int lane = tid & 31, wid = tid >> 5;
    int wm = wid & 3, wn = wid >> 2;
    int gq = lane >> 2, tg = lane & 3;
    int row0 = blockIdx.x * 128;

#pragma unroll
    for (int i = tid; i < 4096; i += 1024) {
        int n = i >> 4, kb = (i & 15) * 8;
        *reinterpret_cast<uint4*>(&Ws[n * WP + kb]) =
            *reinterpret_cast<const uint4*>(&Wt[(size_t)n * 128 + kb]);
    }
    {
        int xr = tid >> 3, xc0 = (tid & 7) * 16;
        int gr = row0 + xr;
        bool rowok = (gr < M);
        const uint4* xrow = reinterpret_cast<const uint4*>(&Xh[(size_t)gr * 128 + xc0]);
#pragma unroll
        for (int j = 0; j < 2; j++) {
            uint4 v = make_uint4(0u, 0u, 0u, 0u);
            if (rowok) v = xrow[j];
            *reinterpret_cast<uint4*>(&Xs[xr * WP + xc0 + j * 8]) = v;
        }
    }
    __syncthreads();
    GEMM_MAIN_AND_EPI()
}

// ---------------------------------------------------------------------------
// aggregation: warp per node, fp16 P rows, 4-edge unroll, fp32 accumulate
// ---------------------------------------------------------------------------
__device__ __forceinline__ float4 agg_node(const __half* __restrict__ P,
                                           const float* __restrict__ R,
                                           float4 b, int w, int lane)
{
    int e0 = g_row_ptr[w], e1 = g_row_ptr[w + 1];
    const uint2* P2 = reinterpret_cast<const uint2*>(P);
    float4 acc = make_float4(0.f, 0.f, 0.f, 0.f);
    int e = e0;
#define ACCV(v) { \
    float2 p0 = __half22float2(*reinterpret_cast<__half2*>(&(v).x)); \
    float2 p1 = __half22float2(*reinterpret_cast<__half2*>(&(v).y)); \
    acc.x += p0.x; acc.y += p0.y; acc.z += p1.x; acc.w += p1.y; }
    for (; e + 3 < e1; e += 4) {
        int u0 = g_esrc[e],     u1 = g_esrc[e + 1];
        int u2 = g_esrc[e + 2], u3 = g_esrc[e + 3];
        uint2 v0 = P2[(size_t)u0 * 32 + lane];
        uint2 v1 = P2[(size_t)u1 * 32 + lane];
        uint2 v2 = P2[(size_t)u2 * 32 + lane];
        uint2 v3 = P2[(size_t)u3 * 32 + lane];
        ACCV(v0); ACCV(v1); ACCV(v2); ACCV(v3);
    }
    for (; e < e1; e++) {
        int u = g_esrc[e];
        uint2 v = P2[(size_t)u * 32 + lane];
        ACCV(v);
    }
#undef ACCV
    float inn = g_in_norm[w];
    float4 r = reinterpret_cast<const float4*>(R)[(size_t)w * 32 + lane];
    float4 o;
    o.x = fmaxf(fmaf(acc.x, inn, b.x), 0.f) + r.x;
    o.y = fmaxf(fmaf(acc.y, inn, b.y), 0.f) + r.y;
    o.z = fmaxf(fmaf(acc.z, inn, b.z), 0.f) + r.z;
    o.w = fmaxf(fmaf(acc.w, inn, b.w), 0.f) + r.w;
    return o;
}

__global__ void k_agg_h(const __half* __restrict__ P, const float* __restrict__ R,
                        const float* __restrict__ bias, int Nn, __half* __restrict__ out)
{
    int w = (int)((blockIdx.x * (size_t)blockDim.x + threadIdx.x) >> 5);
    int lane = threadIdx.x & 31;
    if (w >= Nn) return;
    float4 b = reinterpret_cast<const float4*>(bias)[lane];
    float4 o = agg_node(P, R, b, w, lane);
    __half2 h01 = __floats2half2_rn(o.x, o.y);
    __half2 h23 = __floats2half2_rn(o.z, o.w);
    uint2 u;
    u.x = *reinterpret_cast<uint32_t*>(&h01);
    u.y = *reinterpret_cast<uint32_t*>(&h23);
    reinterpret_cast<uint2*>(out)[(size_t)w * 32 + lane] = u;
}

__global__ void k_agg_f(const __half* __restrict__ P, const float* __restrict__ R,
                        const float* __restrict__ bias, int Nn, float* __restrict__ out)
{
    int w = (int)((blockIdx.x * (size_t)blockDim.x + threadIdx.x) >> 5);
    int lane = threadIdx.x & 31;
    if (w >= Nn) return;
    float4 b = reinterpret_cast<const float4*>(bias)[lane];
    float4 o = agg_node(P, R, b, w, lane);
    reinterpret_cast<float4*>(out)[(size_t)w * 32 + lane] = o;
}

// ---------------------------------------------------------------------------
// readout: warp per graph, binary search on sorted gid; X2 row = [hsum|hmax]
// ---------------------------------------------------------------------------
__global__ void k_readout(const float* __restrict__ H, const int* __restrict__ gid,
                          const float* __restrict__ awW, const float* __restrict__ awb,
                          float* __restrict__ X2, int Nn, int Bg)
{
    int g = (int)((blockIdx.x * (size_t)blockDim.x + threadIdx.x) >> 5);
    int lane = threadIdx.x & 31;
    if (g >= Bg) return;
    int lo = 0, hi = Nn;
    while (lo < hi) { int mid = (lo + hi) >> 1; if (gid[mid] < g) lo = mid + 1; else hi = mid; }
    int lo2 = lo, hi2 = Nn;
    while (lo2 < hi2) { int mid = (lo2 + hi2) >> 1; if (gid[mid] < g + 1) lo2 = mid + 1; else hi2 = mid; }

    float4 a = reinterpret_cast<const float4*>(awW)[lane];
    float ab = awb[0];
    float4 s  = make_float4(0.f, 0.f, 0.f, 0.f);
    float4 mx = make_float4(0.f, 0.f, 0.f, 0.f);   // h >= 0
    const float4* H4 = reinterpret_cast<const float4*>(H);
    for (int i = lo; i < lo2; i++) {
        float4 h = H4[(size_t)i * 32 + lane];
        float d = h.x * a.x + h.y * a.y + h.z * a.z + h.w * a.w;
#pragma unroll
        for (int o = 16; o; o >>= 1) d += __shfl_xor_sync(0xffffffffu, d, o);
        float aw = 1.f / (1.f + expf(-(d + ab)));
        s.x += aw * h.x; s.y += aw * h.y; s.z += aw * h.z; s.w += aw * h.w;
        mx.x = fmaxf(mx.x, h.x); mx.y = fmaxf(mx.y, h.y);
        mx.z = fmaxf(mx.z, h.z); mx.w = fmaxf(mx.w, h.w);
    }
    *reinterpret_cast<float4*>(&X2[(size_t)g * 256 + lane * 4]) = s;
    *reinterpret_cast<float4*>(&X2[(size_t)g * 256 + 128 + lane * 4]) = mx;
}

// ---------------------------------------------------------------------------
// fused MLP head: 8 graphs/block, 128 threads. Stages:
//  1. z1 = bn(relu(g @ orW1 + orb1))                 [8][128]
//  2. orl = z1 @ orW2 + orb2 -> out + smem           [8][T1]
//  3. z2 = bn(relu([g|orl] @ scW1 + scb1))           [8][128]
//  4. out_sc = z2 @ scW2 + scb2                      [8][T2]
// Weights streamed coalesced from global (L2-hot), A rows broadcast from smem.
// ---------------------------------------------------------------------------
__global__ __launch_bounds__(128) void k_head(
    const float* __restrict__ X2,
    const float* __restrict__ orW1, const float* __restrict__ orb1,
    const float* __restrict__ org,  const float* __restrict__ orbeta,
    const float* __restrict__ orW2, const float* __restrict__ orb2,
    const float* __restrict__ scW1, const float* __restrict__ scb1,
    const float* __restrict__ scg,  const float* __restrict__ scbeta,
    const float* __restrict__ scW2, const float* __restrict__ scb2,
    float* __restrict__ out, float* __restrict__ out_sc,
    int Bg, int T1, int T2)
{
    __shared__ float gS[8][256];
    __shared__ float z1S[8][128];
    __shared__ float orlS[8][576];   // T1 <= 576
    __shared__ float z2S[8][128];
    int tid = threadIdx.x;
    int row0 = blockIdx.x * 8;

    // load 8 g rows (guarded)
    for (int i = tid; i < 8 * 64; i += 128) {
        int r = i >> 6, c4 = (i & 63) * 4;
        int gr = row0 + r;
        float4 v = make_float4(0.f, 0.f, 0.f, 0.f);
        if (gr < Bg) v = *reinterpret_cast<const float4*>(&X2[(size_t)gr * 256 + c4]);
        *reinterpret_cast<float4*>(&gS[r][c4]) = v;
    }
    __syncthreads();

    // ---- stage 1: Nc = 128, K = 256 ----
    {
        int gc = tid;
        float acc[8];
#pragma unroll
        for (int r = 0; r < 8; r++) acc[r] = 0.f;
#pragma unroll 4
        for (int k0 = 0; k0 < 256; k0 += 4) {
            float w0 = orW1[(size_t)(k0 + 0) * 128 + gc];
            float w1 = orW1[(size_t)(k0 + 1) * 128 + gc];
            float w2 = orW1[(size_t)(k0 + 2) * 128 + gc];
            float w3 = orW1[(size_t)(k0 + 3) * 128 + gc];
#pragma unroll
            for (int r = 0; r < 8; r++) {
                float4 a = *reinterpret_cast<const float4*>(&gS[r][k0]);
                acc[r] = fmaf(a.x, w0, acc[r]);
                acc[r] = fmaf(a.y, w1, acc[r]);
                acc[r] = fmaf(a.z, w2, acc[r]);
                acc[r] = fmaf(a.w, w3, acc[r]);
            }
        }
        float bv = orb1[gc], gam = org[gc] * BN_INV, bet = orbeta[gc];
#pragma unroll
        for (int r = 0; r < 8; r++)
            z1S[r][gc] = fmaxf(acc[r] + bv, 0.f) * gam + bet;
    }
    __syncthreads();

    // ---- stage 2: Nc = T1, K = 128; write out + orlS ----
    for (int c0 = 0; c0 < T1; c0 += 128) {
        int gc = c0 + tid;
        if (gc < T1) {
            float acc[8];
#pragma unroll
            for (int r = 0; r < 8; r++) acc[r] = 0.f;
#pragma unroll 4
            for (int k0 = 0; k0 < 128; k0 += 4) {
                float w0 = orW2[(size_t)(k0 + 0) * T1 + gc];
                float w1 = orW2[(size_t)(k0 + 1) * T1 + gc];
                float w2 = orW2[(size_t)(k0 + 2) * T1 + gc];
                float w3 = orW2[(size_t)(k0 + 3) * T1 + gc];
#pragma unroll
                for (int r = 0; r < 8; r++) {
                    float4 a = *reinterpret_cast<const float4*>(&z1S[r][k0]);
                    acc[r] = fmaf(a.x, w0, acc[r]);
                    acc[r] = fmaf(a.y, w1, acc[r]);
                    acc[r] = fmaf(a.z, w2, acc[r]);
                    acc[r] = fmaf(a.w, w3, acc[r]);
                }
            }
            float bv = orb2[gc];
#pragma unroll
            for (int r = 0; r < 8; r++) {
                float v = acc[r] + bv;
                orlS[r][gc] = v;
                int gr = row0 + r;
                if (gr < Bg) out[(size_t)gr * T1 + gc] = v;
            }
        }
    }
    __syncthreads();

    // ---- stage 3: Nc = 128, K = 256 + T1 ----
    {
        int gc = tid;
        float acc[8];
#pragma unroll
        for (int r = 0; r < 8; r++) acc[r] = 0.f;
#pragma unroll 4
        for (int k0 = 0; k0 < 256; k0 += 4) {
            float w0 = scW1[(size_t)(k0 + 0) * 128 + gc];
            float w1 = scW1[(size_t)(k0 + 1) * 128 + gc];
            float w2 = scW1[(size_t)(k0 + 2) * 128 + gc];
            float w3 = scW1[(size_t)(k0 + 3) * 128 + gc];
#pragma unroll
            for (int r = 0; r < 8; r++) {
                float4 a = *reinterpret_cast<const float4*>(&gS[r][k0]);
                acc[r] = fmaf(a.x, w0, acc[r]);
                acc[r] = fmaf(a.y, w1, acc[r]);
                acc[r] = fmaf(a.z, w2, acc[r]);
                acc[r] = fmaf(a.w, w3, acc[r]);
            }
        }
        // orl part: T1 is even; step 2
        const float* scW1b = scW1 + (size_t)256 * 128;
#pragma unroll 4
        for (int k0 = 0; k0 < T1; k0 += 2) {
            float w0 = scW1b[(size_t)(k0 + 0) * 128 + gc];
            float w1 = scW1b[(size_t)(k0 + 1) * 128 + gc];
#pragma unroll
            for (int r = 0; r < 8; r++) {
                float2 a = *reinterpret_cast<const float2*>(&orlS[r][k0]);
                acc[r] = fmaf(a.x, w0, acc[r]);
                acc[r] = fmaf(a.y, w1, acc[r]);
            }
        }
        float bv = scb1[gc], gam = scg[gc] * BN_INV, bet = scbeta[gc];
#pragma unroll
        for (int r = 0; r < 8; r++)
            z2S[r][gc] = fmaxf(acc[r] + bv, 0.f) * gam + bet;
    }
    __syncthreads();

    // ---- stage 4: Nc = T2, K = 128 ----
    for (int c0 = 0; c0 < T2; c0 += 128) {
        int gc = c0 + tid;
        if (gc < T2) {
            float acc[8];
#pragma unroll
            for (int r = 0; r < 8; r++) acc[r] = 0.f;
#pragma unroll 4
            for (int k0 = 0; k0 < 128; k0 += 4) {
                float w0 = scW2[(size_t)(k0 + 0) * T2 + gc];
                float w1 = scW2[(size_t)(k0 + 1) * T2 + gc];
                float w2 = scW2[(size_t)(k0 + 2) * T2 + gc];
                float w3 = scW2[(size_t)(k0 + 3) * T2 + gc];
#pragma unroll
                for (int r = 0; r < 8; r++) {
                    float4 a = *reinterpret_cast<const float4*>(&z2S[r][k0]);
                    acc[r] = fmaf(a.x, w0, acc[r]);
                    acc[r] = fmaf(a.y, w1, acc[r]);
                    acc[r] = fmaf(a.z, w2, acc[r]);
                    acc[r] = fmaf(a.w, w3, acc[r]);
                }
            }
            float bv = scb2[gc];
#pragma unroll
            for (int r = 0; r < 8; r++) {
                int gr = row0 + r;
                if (gr < Bg) out_sc[(size_t)gr * T2 + gc] = acc[r] + bv;
            }
        }
    }
}

// ---------------------------------------------------------------------------
// host
// ---------------------------------------------------------------------------
extern "C" void kernel_launch(void* const* d_in, const int* in_sizes, int n_in,
                              void* d_out, int out_size)
{
    const float* feats  = (const float*)d_in[0];
    const int*   src    = (const int*)  d_in[1];
    const int*   dst    = (const int*)  d_in[2];
    const int*   gid    = (const int*)  d_in[3];
    const float* W1     = (const float*)d_in[4];
    const float* b1     = (const float*)d_in[5];
    const float* resW1  = (const float*)d_in[6];
    const float* resb1  = (const float*)d_in[7];
    const float* W2     = (const float*)d_in[8];
    const float* b2     = (const float*)d_in[9];
    const float* resW2  = (const float*)d_in[10];
    const float* resb2  = (const float*)d_in[11];
    const float* awW    = (const float*)d_in[12];
    const float* awb    = (const float*)d_in[13];
    const float* orW1   = (const float*)d_in[14];
    const float* orb1   = (const float*)d_in[15];
    const float* org    = (const float*)d_in[16];
    const float* orbeta = (const float*)d_in[17];
    const float* orW2   = (const float*)d_in[18];
    const float* orb2   = (const float*)d_in[19];
    const float* scW1   = (const float*)d_in[20];
    const float* scb1   = (const float*)d_in[21];
    const float* scg    = (const float*)d_in[22];
    const float* scbeta = (const float*)d_in[23];
    const float* scW2   = (const float*)d_in[24];
    const float* scb2   = (const float*)d_in[25];

    int N  = in_sizes[0] / HD;
    int E  = in_sizes[1];
    int T1 = in_sizes[19];
    int T2 = in_sizes[25];
    int B  = out_size / (T1 + T2);

    float* out    = (float*)d_out;
    float* out_sc = out + (size_t)B * T1;

    void *pPh, *pRf, *pHh, *pHf, *pX2, *pON, *pWt;
    cudaGetSymbolAddress(&pPh, g_Ph);
    cudaGetSymbolAddress(&pRf, g_Rf);
    cudaGetSymbolAddress(&pHh, g_Hh);
    cudaGetSymbolAddress(&pHf, g_Hf);
    cudaGetSymbolAddress(&pX2, g_X2);
    cudaGetSymbolAddress(&pON, g_out_norm);
    cudaGetSymbolAddress(&pWt, g_Wt);
    __half* Ph = (__half*)pPh;
    float*  Rf = (float*)pRf;
    __half* Hh = (__half*)pHh;
    float*  Hf = (float*)pHf;
    float*  X2 = (float*)pX2;
    float*  ONm = (float*)pON;
    __half* Wt0 = (__half*)pWt;
    __half* Wt1 = Wt0 + (size_t)256 * 128;

    cudaFuncSetAttribute(k_gemm_l1,  cudaFuncAttributeMaxDynamicSharedMemorySize, GEMM_SMEM);
    cudaFuncSetAttribute(k_gemm_l2h, cudaFuncAttributeMaxDynamicSharedMemorySize, GEMM_SMEM);

    int eb = (E + 255) / 256;
    int nb = (N + SCAN_CHUNK - 1) / SCAN_CHUNK;
    int gb = (N + 127) / 128;
    int wb = (N + 7) / 8;

    // launches: 1 zero, 2 wconv, 3 deg, 4 normchunk, 5 scan2,
    //           6 gemm_l1 <- ncu skip-5 profile slot
    k_zero<<<(N + 255) / 256, 256>>>(N);
    k_wconv<<<(2 * 256 * 128 + 255) / 256, 256>>>(W1, resW1, W2, resW2);
    k_deg<<<eb, 256>>>(src, dst, E);
    k_normchunk<<<nb, 256>>>(N);
    k_scan2<<<nb, 256>>>(N);

    k_gemm_l1<<<gb, 1024, GEMM_SMEM>>>(feats, Wt0, resb1, ONm, Ph, Rf, N);

    k_build<<<eb, 256>>>(src, dst, E);
    k_agg_h<<<wb, 256>>>(Ph, Rf, b1, N, Hh);                 // H1 fp16

    k_gemm_l2h<<<gb, 1024, GEMM_SMEM>>>(Hh, Wt1, resb2, ONm, Ph, Rf, N);
    k_agg_f<<<wb, 256>>>(Ph, Rf, b2, N, Hf);                 // H2 fp32

    k_readout<<<(B + 7) / 8, 256>>>(Hf, gid, awW, awb, X2, N, B);

    k_head<<<(B + 7) / 8, 128>>>(X2, orW1, orb1, org, orbeta, orW2, orb2,
                                 scW1, scb1, scg, scbeta, scW2, scb2,
                                 out, out_sc, B, T1, T2);
}

// round 14
// speedup vs baseline: 1.5632x; 1.0039x over previous
#include <cuda_runtime.h>
#include <cuda_fp16.h>
#include <math.h>
#include <stdint.h>

// ---------------------------------------------------------------------------
// GCNJointPredictor, round 14:
//  - SERIAL stream-0 chain (R11 skeleton; the R12/R13 stream fork killed the
//    container twice -> multi-stream is off-limits in this harness)
//  - H2 stored fp16 (reuses g_Hh; readout reads fp16) -> kills 102MB roundtrip
//  - everything else identical to R11 (555.0us best)
// ---------------------------------------------------------------------------

#define NMAX 100000
#define EMAX 3200000
#define BMAX 4096
#define HD   128
#define BN_INV 0.9999950000374997f
#define SCAN_CHUNK 1024

// ---- scratch (device globals) ----
__device__ __align__(16) __half g_Ph[(size_t)NMAX * HD];    // P (both layers)
__device__ __align__(16) float  g_Rf[(size_t)NMAX * HD];    // R (both layers)
__device__ __align__(16) __half g_Hh[(size_t)NMAX * HD];    // H1 then H2 (fp16)
__device__ __align__(16) float  g_X2[(size_t)BMAX * 256];   // [hsum|hmax]
__device__ __align__(16) __half g_Wt[2][256 * 128];         // [layer][n][k] fp16
__device__ int   g_deg_src[NMAX];
__device__ int   g_deg_dst[NMAX];
__device__ float g_out_norm[NMAX];
__device__ float g_in_norm[NMAX];
__device__ int   g_row_ptr[NMAX + 1];
__device__ int   g_cursor[NMAX];
__device__ int   g_esrc[EMAX];
__device__ int   g_bsum[256];

// ---------------------------------------------------------------------------
__global__ void k_zero(int Nn) {
    int i = blockIdx.x * blockDim.x + threadIdx.x;
    if (i < Nn) { g_deg_src[i] = 0; g_deg_dst[i] = 0; }
}

// one-shot weight transpose to fp16: Wt[n][k] = half(W[k][n])
__global__ void k_wconv(const float* __restrict__ W1, const float* __restrict__ rW1,
                        const float* __restrict__ W2, const float* __restrict__ rW2)
{
    int i = blockIdx.x * blockDim.x + threadIdx.x;
    if (i >= 2 * 256 * 128) return;
    int layer = i >> 15;
    int j = i & 32767;
    int n = j >> 7, k = j & 127;
    const float* src = (layer == 0) ? ((n < 128) ? W1 : rW1)
                                    : ((n < 128) ? W2 : rW2);
    g_Wt[layer][(size_t)n * 128 + k] = __float2half(src[(size_t)k * 128 + (n & 127)]);
}

__global__ void k_deg(const int* __restrict__ src, const int* __restrict__ dst, int E) {
    int e = blockIdx.x * blockDim.x + threadIdx.x;
    if (e < E) {
        atomicAdd(&g_deg_src[src[e]], 1);
        atomicAdd(&g_deg_dst[dst[e]], 1);
    }
}

// fused: norms + per-chunk sum of deg_dst
__global__ void k_normchunk(int Nn) {
    __shared__ int sdata[256];
    int base = blockIdx.x * SCAN_CHUNK;
    int s = 0;
    for (int i = threadIdx.x; i < SCAN_CHUNK; i += 256) {
        int idx = base + i;
        if (idx < Nn) {
            int ds = g_deg_src[idx], dd = g_deg_dst[idx];
            g_out_norm[idx] = rsqrtf((float)max(ds, 1));
            g_in_norm[idx]  = rsqrtf((float)max(dd, 1));
            s += dd;
        }
    }
    sdata[threadIdx.x] = s;
    __syncthreads();
    for (int off = 128; off > 0; off >>= 1) {
        if (threadIdx.x < off) sdata[threadIdx.x] += sdata[threadIdx.x + off];
        __syncthreads();
    }
    if (threadIdx.x == 0) g_bsum[blockIdx.x] = sdata[0];
}

// merged scan: per-block offset + local scan -> row_ptr/cursor
__global__ void k_scan2(int Nn) {
    __shared__ int s0[SCAN_CHUNK];
    __shared__ int s1[SCAN_CHUNK];
    __shared__ int rs[256];
    int t = threadIdx.x;
    int base = blockIdx.x * SCAN_CHUNK;

    int p = 0;
    for (int i = t; i < blockIdx.x; i += 256) p += g_bsum[i];
    rs[t] = p;
    __syncthreads();
    for (int o = 128; o > 0; o >>= 1) {
        if (t < o) rs[t] += rs[t + o];
        __syncthreads();
    }
    int off = rs[0];

    for (int i = t; i < SCAN_CHUNK; i += 256) {
        int idx = base + i;
        s0[i] = (idx < Nn) ? g_deg_dst[idx] : 0;
    }
    __syncthreads();
    int* a = s0; int* b = s1;
    for (int d = 1; d < SCAN_CHUNK; d <<= 1) {
        for (int i = t; i < SCAN_CHUNK; i += 256)
            b[i] = a[i] + (i >= d ? a[i - d] : 0);
        __syncthreads();
        int* tmp = a; a = b; b = tmp;
    }
    for (int i = t; i < SCAN_CHUNK; i += 256) {
        int idx = base + i;
        if (idx < Nn) {
            int ex = off + (i > 0 ? a[i - 1] : 0);
            g_row_ptr[idx] = ex;
            g_cursor[idx]  = ex;
        }
    }
    if (blockIdx.x == gridDim.x - 1 && t == 0)
        g_row_ptr[Nn] = off + a[SCAN_CHUNK - 1];
}

__global__ void k_build(const int* __restrict__ src, const int* __restrict__ dst, int E) {
    int e = blockIdx.x * blockDim.x + threadIdx.x;
    if (e < E) {
        int p = atomicAdd(&g_cursor[dst[e]], 1);
        g_esrc[p] = src[e];
    }
}

// ---------------------------------------------------------------------------
// fused fp16 tensor-core GEMM core (one barrier, W+X smem resident)
// block 128 rows x 256 cols, 1024 thr (32 warps, 4M x 8N), warp tile 32x32
// ---------------------------------------------------------------------------
#define WP 136
#define GEMM_SMEM ((256 * WP + 128 * WP) * 2)   // 104448 bytes

#define MMA_F16(c, a0, a1, a2, a3, b0, b1)                                   \
    asm volatile(                                                            \
        "mma.sync.aligned.m16n8k16.row.col.f32.f16.f16.f32 "                 \
        "{%0,%1,%2,%3}, {%4,%5,%6,%7}, {%8,%9}, {%0,%1,%2,%3};"              \
        : "+f"((c)[0]), "+f"((c)[1]), "+f"((c)[2]), "+f"((c)[3])             \
        : "r"(a0), "r"(a1), "r"(a2), "r"(a3), "r"(b0), "r"(b1))

#define GEMM_MAIN_AND_EPI()                                                  \
    float acc[2][4][4];                                                      \
    _Pragma("unroll")                                                        \
    for (int mt = 0; mt < 2; mt++)                                           \
        _Pragma("unroll")                                                    \
        for (int nt = 0; nt < 4; nt++)                                       \
            _Pragma("unroll")                                                \
            for (int q = 0; q < 4; q++) acc[mt][nt][q] = 0.f;                \
    _Pragma("unroll")                                                        \
    for (int c = 0; c < 8; c++) {                                            \
        int kk = c * 16;                                                     \
        uint32_t a[2][4];                                                    \
        _Pragma("unroll")                                                    \
        for (int mt = 0; mt < 2; mt++) {                                     \
            int r = wm * 32 + mt * 16 + gq;                                  \
            a[mt][0] = *reinterpret_cast<uint32_t*>(&Xs[r * WP + kk + tg * 2]);          \
            a[mt][1] = *reinterpret_cast<uint32_t*>(&Xs[(r + 8) * WP + kk + tg * 2]);    \
            a[mt][2] = *reinterpret_cast<uint32_t*>(&Xs[r * WP + kk + 8 + tg * 2]);      \
            a[mt][3] = *reinterpret_cast<uint32_t*>(&Xs[(r + 8) * WP + kk + 8 + tg * 2]);\
        }                                                                    \
        _Pragma("unroll")                                                    \
        for (int nt = 0; nt < 4; nt++) {                                     \
            int nb = wn * 32 + nt * 8 + gq;                                  \
            uint32_t b0 = *reinterpret_cast<uint32_t*>(&Ws[nb * WP + kk + tg * 2]);      \
            uint32_t b1 = *reinterpret_cast<uint32_t*>(&Ws[nb * WP + kk + 8 + tg * 2]);  \
            _Pragma("unroll")                                                \
            for (int mt = 0; mt < 2; mt++)                                   \
                MMA_F16(acc[mt][nt], a[mt][0], a[mt][1], a[mt][2], a[mt][3], b0, b1);    \
        }                                                                    \
    }                                                                        \
    _Pragma("unroll")                                                        \
    for (int mt = 0; mt < 2; mt++) {                                         \
        int r0 = row0 + wm * 32 + mt * 16 + gq;                              \
        int r1 = r0 + 8;                                                     \
        if (wn < 4) {                                                        \
            float s0 = (r0 < M) ? rowscale[r0] : 0.f;                        \
            float s1 = (r1 < M) ? rowscale[r1] : 0.f;                        \
            _Pragma("unroll")                                                \
            for (int nt = 0; nt < 4; nt++) {                                 \
                int c = wn * 32 + nt * 8 + tg * 2;                           \
                float* a = acc[mt][nt];                                      \
                if (r0 < M)                                                  \
                    *reinterpret_cast<__half2*>(&Pout[(size_t)r0 * 128 + c]) =           \
                        __floats2half2_rn(a[0] * s0, a[1] * s0);             \
                if (r1 < M)                                                  \
                    *reinterpret_cast<__half2*>(&Pout[(size_t)r1 * 128 + c]) =           \
                        __floats2half2_rn(a[2] * s1, a[3] * s1);             \
            }                                                                \
        } else {                                                             \
            _Pragma("unroll")                                                \
            for (int nt = 0; nt < 4; nt++) {                                 \
                int c = (wn - 4) * 32 + nt * 8 + tg * 2;                     \
                float* a = acc[mt][nt];                                      \
                float b0 = resb[c], b1 = resb[c + 1];                        \
                if (r0 < M)                                                  \
                    *reinterpret_cast<float2*>(&RoutF[(size_t)r0 * 128 + c]) =           \
                        make_float2(fmaxf(a[0] + b0, 0.f), fmaxf(a[1] + b1, 0.f));       \
                if (r1 < M)                                                  \
                    *reinterpret_cast<float2*>(&RoutF[(size_t)r1 * 128 + c]) =           \
                        make_float2(fmaxf(a[2] + b0, 0.f), fmaxf(a[3] + b1, 0.f));       \
            }                                                                \
        }                                                                    \
    }

// ---- layer 1: X from fp32 global ----
__global__ __launch_bounds__(1024) void k_gemm_l1(
    const float* __restrict__ X, const __half* __restrict__ Wt,
    const float* __restrict__ resb, const float* __restrict__ rowscale,
    __half* __restrict__ Pout, float* __restrict__ RoutF, int M)
{
    extern __shared__ __half sm[];
    __half* Ws = sm;
    __half* Xs = sm + 256 * WP;
    int tid = threadIdx.x;
    int lane = tid & 31, wid = tid >> 5;
    int wm = wid & 3, wn = wid >> 2;
    int gq = lane >> 2, tg = lane & 3;
    int row0 = blockIdx.x * 128;

#pragma unroll
    for (int i = tid; i < 4096; i += 1024) {
        int n = i >> 4, kb = (i & 15) * 8;
        *reinterpret_cast<uint4*>(&Ws[n * WP + kb]) =
            *reinterpret_cast<const uint4*>(&Wt[(size_t)n * 128 + kb]);
    }
    {
        int xr = tid >> 3, xc0 = (tid & 7) * 16;
        int gr = row0 + xr;
        bool rowok = (gr < M);
        const float4* xrow = reinterpret_cast<const float4*>(&X[(size_t)gr * 128 + xc0]);
#pragma unroll
        for (int j = 0; j < 4; j++) {
            float4 v = make_float4(0.f, 0.f, 0.f, 0.f);
            if (rowok) v = xrow[j];
            __half2 h01 = __floats2half2_rn(v.x, v.y);
            __half2 h23 = __floats2half2_rn(v.z, v.w);
            uint2 u;
            u.x = *reinterpret_cast<uint32_t*>(&h01);
            u.y = *reinterpret_cast<uint32_t*>(&h23);
            *reinterpret_cast<uint2*>(&Xs[xr * WP + xc0 + j * 4]) = u;
        }
    }
    __syncthreads();
    GEMM_MAIN_AND_EPI()
}

// ---- layer 2: X from fp16 global (H1) ----
__global__ __launch_bounds__(1024) void k_gemm_l2h(
    const __half* __restrict__ Xh, const __half* __restrict__ Wt,
    const float* __restrict__ resb, const float* __restrict__ rowscale,
    __half* __restrict__ Pout, float* __restrict__ RoutF, int M)
{
    extern __shared__ __half sm[];
    __half* Ws = sm;
    __half* Xs = sm + 256 * WP;
    int tid = threadIdx.x;
    int lane = tid & 31, wid = tid >> 5;
    int wm = wid & 3, wn = wid >> 2;
    int gq = lane >> 2, tg = lane & 3;
    int row0 = blockIdx.x * 128;

#pragma unroll
    for (int i = tid; i < 4096; i += 1024) {
        int n = i >> 4, kb = (i & 15) * 8;
        *reinterpret_cast<uint4*>(&Ws[n * WP + kb]) =
            *reinterpret_cast<const uint4*>(&Wt[(size_t)n * 128 + kb]);
    }
    {
        int xr = tid >> 3, xc0 = (tid & 7) * 16;
        int gr = row0 + xr;
        bool rowok = (gr < M);
        const uint4* xrow = reinterpret_cast<const uint4*>(&Xh[(size_t)gr * 128 + xc0]);
#pragma unroll
        for (int j = 0; j < 2; j++) {
            uint4 v = make_uint4(0u, 0u, 0u, 0u);
            if (rowok) v = xrow[j];
            *reinterpret_cast<uint4*>(&Xs[xr * WP + xc0 + j * 8]) = v;
        }
    }
    __syncthreads();
    GEMM_MAIN_AND_EPI()
}

// ---------------------------------------------------------------------------
// aggregation: warp per node, fp16 P rows, 4-edge unroll, fp32 accumulate
// ---------------------------------------------------------------------------
__device__ __forceinline__ float4 agg_node(const __half* __restrict__ P,
                                           const float* __restrict__ R,
                                           float4 b, int w, int lane)
{
    int e0 = g_row_ptr[w], e1 = g_row_ptr[w + 1];
    const uint2* P2 = reinterpret_cast<const uint2*>(P);
    float4 acc = make_float4(0.f, 0.f, 0.f, 0.f);
    int e = e0;
#define ACCV(v) { \
    float2 p0 = __half22float2(*reinterpret_cast<__half2*>(&(v).x)); \
    float2 p1 = __half22float2(*reinterpret_cast<__half2*>(&(v).y)); \
    acc.x += p0.x; acc.y += p0.y; acc.z += p1.x; acc.w += p1.y; }
    for (; e + 3 < e1; e += 4) {
        int u0 = g_esrc[e],     u1 = g_esrc[e + 1];
        int u2 = g_esrc[e + 2], u3 = g_esrc[e + 3];
        uint2 v0 = P2[(size_t)u0 * 32 + lane];
        uint2 v1 = P2[(size_t)u1 * 32 + lane];
        uint2 v2 = P2[(size_t)u2 * 32 + lane];
        uint2 v3 = P2[(size_t)u3 * 32 + lane];
        ACCV(v0); ACCV(v1); ACCV(v2); ACCV(v3);
    }
    for (; e < e1; e++) {
        int u = g_esrc[e];
        uint2 v = P2[(size_t)u * 32 + lane];
        ACCV(v);
    }
#undef ACCV
    float inn = g_in_norm[w];
    float4 r = reinterpret_cast<const float4*>(R)[(size_t)w * 32 + lane];
    float4 o;
    o.x = fmaxf(fmaf(acc.x, inn, b.x), 0.f) + r.x;
    o.y = fmaxf(fmaf(acc.y, inn, b.y), 0.f) + r.y;
    o.z = fmaxf(fmaf(acc.z, inn, b.z), 0.f) + r.z;
    o.w = fmaxf(fmaf(acc.w, inn, b.w), 0.f) + r.w;
    return o;
}

__global__ void k_agg_h(const __half* __restrict__ P, const float* __restrict__ R,
                        const float* __restrict__ bias, int Nn, __half* __restrict__ out)
{
    int w = (int)((blockIdx.x * (size_t)blockDim.x + threadIdx.x) >> 5);
    int lane = threadIdx.x & 31;
    if (w >= Nn) return;
    float4 b = reinterpret_cast<const float4*>(bias)[lane];
    float4 o = agg_node(P, R, b, w, lane);
    __half2 h01 = __floats2half2_rn(o.x, o.y);
    __half2 h23 = __floats2half2_rn(o.z, o.w);
    uint2 u;
    u.x = *reinterpret_cast<uint32_t*>(&h01);
    u.y = *reinterpret_cast<uint32_t*>(&h23);
    reinterpret_cast<uint2*>(out)[(size_t)w * 32 + lane] = u;
}

// ---------------------------------------------------------------------------
// readout: warp per graph, H in fp16; X2 row = [hsum|hmax]
// ---------------------------------------------------------------------------
__global__ void k_readout(const __half* __restrict__ H, const int* __restrict__ gid,
                          const float* __restrict__ awW, const float* __restrict__ awb,
                          float* __restrict__ X2, int Nn, int Bg)
{
    int g = (int)((blockIdx.x * (size_t)blockDim.x + threadIdx.x) >> 5);
    int lane = threadIdx.x & 31;
    if (g >= Bg) return;
    int lo = 0, hi = Nn;
    while (lo < hi) { int mid = (lo + hi) >> 1; if (gid[mid] < g) lo = mid + 1; else hi = mid; }
    int lo2 = lo, hi2 = Nn;
    while (lo2 < hi2) { int mid = (lo2 + hi2) >> 1; if (gid[mid] < g + 1) lo2 = mid + 1; else hi2 = mid; }

    float4 a = reinterpret_cast<const float4*>(awW)[lane];
    float ab = awb[0];
    float4 s  = make_float4(0.f, 0.f, 0.f, 0.f);
    float4 mx = make_float4(0.f, 0.f, 0.f, 0.f);   // h >= 0
    const uint2* H2v = reinterpret_cast<const uint2*>(H);
    for (int i = lo; i < lo2; i++) {
        uint2 hv = H2v[(size_t)i * 32 + lane];
        float2 h01 = __half22float2(*reinterpret_cast<__half2*>(&hv.x));
        float2 h23 = __half22float2(*reinterpret_cast<__half2*>(&hv.y));
        float4 h = make_float4(h01.x, h01.y, h23.x, h23.y);
        float d = h.x * a.x + h.y * a.y + h.z * a.z + h.w * a.w;
#pragma unroll
        for (int o = 16; o; o >>= 1) d += __shfl_xor_sync(0xffffffffu, d, o);
        float aw = 1.f / (1.f + expf(-(d + ab)));
        s.x += aw * h.x; s.y += aw * h.y; s.z += aw * h.z; s.w += aw * h.w;
        mx.x = fmaxf(mx.x, h.x); mx.y = fmaxf(mx.y, h.y);
        mx.z = fmaxf(mx.z, h.z); mx.w = fmaxf(mx.w, h.w);
    }
    *reinterpret_cast<float4*>(&X2[(size_t)g * 256 + lane * 4]) = s;
    *reinterpret_cast<float4*>(&X2[(size_t)g * 256 + 128 + lane * 4]) = mx;
}

// ---------------------------------------------------------------------------
// fused MLP head: 8 graphs/block, 128 threads
// ---------------------------------------------------------------------------
__global__ __launch_bounds__(128) void k_head(
    const float* __restrict__ X2,
    const float* __restrict__ orW1, const float* __restrict__ orb1,
    const float* __restrict__ org,  const float* __restrict__ orbeta,
    const float* __restrict__ orW2, const float* __restrict__ orb2,
    const float* __restrict__ scW1, const float* __restrict__ scb1,
    const float* __restrict__ scg,  const float* __restrict__ scbeta,
    const float* __restrict__ scW2, const float* __restrict__ scb2,
    float* __restrict__ out, float* __restrict__ out_sc,
    int Bg, int T1, int T2)
{
    __shared__ float gS[8][256];
    __shared__ float z1S[8][128];
    __shared__ float orlS[8][576];   // T1 <= 576
    __shared__ float z2S[8][128];
    int tid = threadIdx.x;
    int row0 = blockIdx.x * 8;

    for (int i = tid; i < 8 * 64; i += 128) {
        int r = i >> 6, c4 = (i & 63) * 4;
        int gr = row0 + r;
        float4 v = make_float4(0.f, 0.f, 0.f, 0.f);
        if (gr < Bg) v = *reinterpret_cast<const float4*>(&X2[(size_t)gr * 256 + c4]);
        *reinterpret_cast<float4*>(&gS[r][c4]) = v;
    }
    __syncthreads();

    // stage 1
    {
        int gc = tid;
        float acc[8];
#pragma unroll
        for (int r = 0; r < 8; r++) acc[r] = 0.f;
#pragma unroll 4
        for (int k0 = 0; k0 < 256; k0 += 4) {
            float w0 = orW1[(size_t)(k0 + 0) * 128 + gc];
            float w1 = orW1[(size_t)(k0 + 1) * 128 + gc];
            float w2 = orW1[(size_t)(k0 + 2) * 128 + gc];
            float w3 = orW1[(size_t)(k0 + 3) * 128 + gc];
#pragma unroll
            for (int r = 0; r < 8; r++) {
                float4 a = *reinterpret_cast<const float4*>(&gS[r][k0]);
                acc[r] = fmaf(a.x, w0, acc[r]);
                acc[r] = fmaf(a.y, w1, acc[r]);
                acc[r] = fmaf(a.z, w2, acc[r]);
                acc[r] = fmaf(a.w, w3, acc[r]);
            }
        }
        float bv = orb1[gc], gam = org[gc] * BN_INV, bet = orbeta[gc];
#pragma unroll
        for (int r = 0; r < 8; r++)
            z1S[r][gc] = fmaxf(acc[r] + bv, 0.f) * gam + bet;
    }
    __syncthreads();

    // stage 2
    for (int c0 = 0; c0 < T1; c0 += 128) {
        int gc = c0 + tid;
        if (gc < T1) {
            float acc[8];
#pragma unroll
            for (int r = 0; r < 8; r++) acc[r] = 0.f;
#pragma unroll 4
            for (int k0 = 0; k0 < 128; k0 += 4) {
                float w0 = orW2[(size_t)(k0 + 0) * T1 + gc];
                float w1 = orW2[(size_t)(k0 + 1) * T1 + gc];
                float w2 = orW2[(size_t)(k0 + 2) * T1 + gc];
                float w3 = orW2[(size_t)(k0 + 3) * T1 + gc];
#pragma unroll
                for (int r = 0; r < 8; r++) {
                    float4 a = *reinterpret_cast<const float4*>(&z1S[r][k0]);
                    acc[r] = fmaf(a.x, w0, acc[r]);
                    acc[r] = fmaf(a.y, w1, acc[r]);
                    acc[r] = fmaf(a.z, w2, acc[r]);
                    acc[r] = fmaf(a.w, w3, acc[r]);
                }
            }
            float bv = orb2[gc];
#pragma unroll
            for (int r = 0; r < 8; r++) {
                float v = acc[r] + bv;
                orlS[r][gc] = v;
                int gr = row0 + r;
                if (gr < Bg) out[(size_t)gr * T1 + gc] = v;
            }
        }
    }
    __syncthreads();

    // stage 3
    {
        int gc = tid;
        float acc[8];
#pragma unroll
        for (int r = 0; r < 8; r++) acc[r] = 0.f;
#pragma unroll 4
        for (int k0 = 0; k0 < 256; k0 += 4) {
            float w0 = scW1[(size_t)(k0 + 0) * 128 + gc];
            float w1 = scW1[(size_t)(k0 + 1) * 128 + gc];
            float w2 = scW1[(size_t)(k0 + 2) * 128 + gc];
            float w3 = scW1[(size_t)(k0 + 3) * 128 + gc];
#pragma unroll
            for (int r = 0; r < 8; r++) {
                float4 a = *reinterpret_cast<const float4*>(&gS[r][k0]);
                acc[r] = fmaf(a.x, w0, acc[r]);
                acc[r] = fmaf(a.y, w1, acc[r]);
                acc[r] = fmaf(a.z, w2, acc[r]);
                acc[r] = fmaf(a.w, w3, acc[r]);
            }
        }
        const float* scW1b = scW1 + (size_t)256 * 128;
#pragma unroll 4
        for (int k0 = 0; k0 < T1; k0 += 2) {
            float w0 = scW1b[(size_t)(k0 + 0) * 128 + gc];
            float w1 = scW1b[(size_t)(k0 + 1) * 128 + gc];
#pragma unroll
            for (int r = 0; r < 8; r++) {
                float2 a = *reinterpret_cast<const float2*>(&orlS[r][k0]);
                acc[r] = fmaf(a.x, w0, acc[r]);
                acc[r] = fmaf(a.y, w1, acc[r]);
            }
        }
        float bv = scb1[gc], gam = scg[gc] * BN_INV, bet = scbeta[gc];
#pragma unroll
        for (int r = 0; r < 8; r++)
            z2S[r][gc] = fmaxf(acc[r] + bv, 0.f) * gam + bet;
    }
    __syncthreads();

    // stage 4
    for (int c0 = 0; c0 < T2; c0 += 128) {
        int gc = c0 + tid;
        if (gc < T2) {
            float acc[8];
#pragma unroll
            for (int r = 0; r < 8; r++) acc[r] = 0.f;
#pragma unroll 4
            for (int k0 = 0; k0 < 128; k0 += 4) {
                float w0 = scW2[(size_t)(k0 + 0) * T2 + gc];
                float w1 = scW2[(size_t)(k0 + 1) * T2 + gc];
                float w2 = scW2[(size_t)(k0 + 2) * T2 + gc];
                float w3 = scW2[(size_t)(k0 + 3) * T2 + gc];
#pragma unroll
                for (int r = 0; r < 8; r++) {
                    float4 a = *reinterpret_cast<const float4*>(&z2S[r][k0]);
                    acc[r] = fmaf(a.x, w0, acc[r]);
                    acc[r] = fmaf(a.y, w1, acc[r]);
                    acc[r] = fmaf(a.z, w2, acc[r]);
                    acc[r] = fmaf(a.w, w3, acc[r]);
                }
            }
            float bv = scb2[gc];
#pragma unroll
            for (int r = 0; r < 8; r++) {
                int gr = row0 + r;
                if (gr < Bg) out_sc[(size_t)gr * T2 + gc] = acc[r] + bv;
            }
        }
    }
}

// ---------------------------------------------------------------------------
// host (pure stream-0; no streams/events — graph-capture safe)
// ---------------------------------------------------------------------------
extern "C" void kernel_launch(void* const* d_in, const int* in_sizes, int n_in,
                              void* d_out, int out_size)
{
    const float* feats  = (const float*)d_in[0];
    const int*   src    = (const int*)  d_in[1];
    const int*   dst    = (const int*)  d_in[2];
    const int*   gid    = (const int*)  d_in[3];
    const float* W1     = (const float*)d_in[4];
    const float* b1     = (const float*)d_in[5];
    const float* resW1  = (const float*)d_in[6];
    const float* resb1  = (const float*)d_in[7];
    const float* W2     = (const float*)d_in[8];
    const float* b2     = (const float*)d_in[9];
    const float* resW2  = (const float*)d_in[10];
    const float* resb2  = (const float*)d_in[11];
    const float* awW    = (const float*)d_in[12];
    const float* awb    = (const float*)d_in[13];
    const float* orW1   = (const float*)d_in[14];
    const float* orb1   = (const float*)d_in[15];
    const float* org    = (const float*)d_in[16];
    const float* orbeta = (const float*)d_in[17];
    const float* orW2   = (const float*)d_in[18];
    const float* orb2   = (const float*)d_in[19];
    const float* scW1   = (const float*)d_in[20];
    const float* scb1   = (const float*)d_in[21];
    const float* scg    = (const float*)d_in[22];
    const float* scbeta = (const float*)d_in[23];
    const float* scW2   = (const float*)d_in[24];
    const float* scb2   = (const float*)d_in[25];

    int N  = in_sizes[0] / HD;
    int E  = in_sizes[1];
    int T1 = in_sizes[19];
    int T2 = in_sizes[25];
    int B  = out_size / (T1 + T2);

    float* out    = (float*)d_out;
    float* out_sc = out + (size_t)B * T1;

    void *pPh, *pRf, *pHh, *pX2, *pON, *pWt;
    cudaGetSymbolAddress(&pPh, g_Ph);
    cudaGetSymbolAddress(&pRf, g_Rf);
    cudaGetSymbolAddress(&pHh, g_Hh);
    cudaGetSymbolAddress(&pX2, g_X2);
    cudaGetSymbolAddress(&pON, g_out_norm);
    cudaGetSymbolAddress(&pWt, g_Wt);
    __half* Ph = (__half*)pPh;
    float*  Rf = (float*)pRf;
    __half* Hh = (__half*)pHh;
    float*  X2 = (float*)pX2;
    float*  ONm = (float*)pON;
    __half* Wt0 = (__half*)pWt;
    __half* Wt1 = Wt0 + (size_t)256 * 128;

    cudaFuncSetAttribute(k_gemm_l1,  cudaFuncAttributeMaxDynamicSharedMemorySize, GEMM_SMEM);
    cudaFuncSetAttribute(k_gemm_l2h, cudaFuncAttributeMaxDynamicSharedMemorySize, GEMM_SMEM);

    int eb = (E + 255) / 256;
    int nb = (N + SCAN_CHUNK - 1) / SCAN_CHUNK;
    int gb = (N + 127) / 128;
    int wb = (N + 7) / 8;

    // launches: 1 zero, 2 wconv, 3 deg, 4 normchunk, 5 scan2,
    //           6 gemm_l1 <- ncu skip-5 profile slot
    k_zero<<<(N + 255) / 256, 256>>>(N);
    k_wconv<<<(2 * 256 * 128 + 255) / 256, 256>>>(W1, resW1, W2, resW2);
    k_deg<<<eb, 256>>>(src, dst, E);
    k_normchunk<<<nb, 256>>>(N);
    k_scan2<<<nb, 256>>>(N);

    k_gemm_l1<<<gb, 1024, GEMM_SMEM>>>(feats, Wt0, resb1, ONm, Ph, Rf, N);

    k_build<<<eb, 256>>>(src, dst, E);
    k_agg_h<<<wb, 256>>>(Ph, Rf, b1, N, Hh);                 // H1 fp16

    k_gemm_l2h<<<gb, 1024, GEMM_SMEM>>>(Hh, Wt1, resb2, ONm, Ph, Rf, N);
    k_agg_h<<<wb, 256>>>(Ph, Rf, b2, N, Hh);                 // H2 fp16 (reuse)

    k_readout<<<(B + 7) / 8, 256>>>(Hh, gid, awW, awb, X2, N, B);

    k_head<<<(B + 7) / 8, 128>>>(X2, orW1, orb1, org, orbeta, orW2, orb2,
                                 scW1, scb1, scg, scbeta, scW2, scb2,
                                 out, out_sc, B, T1, T2);
}

// round 16
// speedup vs baseline: 1.5912x; 1.0179x over previous
#include <cuda_runtime.h>
#include <cuda_fp16.h>
#include <math.h>
#include <stdint.h>

// ---------------------------------------------------------------------------
// GCNJointPredictor, round 16 (resubmit of R15; container infra failure):
//  - R stored fp16 (both layers): H was already fp16-rounded post-add, so this
//    adds ~1 ulp; saves ~154MB of R traffic across gemm/agg
//  - k_zero + k_wconv merged into k_init (one launch fewer)
//  - serial stream-0 chain, rest = R14 (552.9us best)
// ---------------------------------------------------------------------------

#define NMAX 100000
#define EMAX 3200000
#define BMAX 4096
#define HD   128
#define BN_INV 0.9999950000374997f
#define SCAN_CHUNK 1024

// ---- scratch (device globals) ----
__device__ __align__(16) __half g_Ph[(size_t)NMAX * HD];    // P (both layers)
__device__ __align__(16) __half g_Rh[(size_t)NMAX * HD];    // R fp16 (both layers)
__device__ __align__(16) __half g_Hh[(size_t)NMAX * HD];    // H1 then H2 (fp16)
__device__ __align__(16) float  g_X2[(size_t)BMAX * 256];   // [hsum|hmax]
__device__ __align__(16) __half g_Wt[2][256 * 128];         // [layer][n][k] fp16
__device__ int   g_deg_src[NMAX];
__device__ int   g_deg_dst[NMAX];
__device__ float g_out_norm[NMAX];
__device__ float g_in_norm[NMAX];
__device__ int   g_row_ptr[NMAX + 1];
__device__ int   g_cursor[NMAX];
__device__ int   g_esrc[EMAX];
__device__ int   g_bsum[256];

// ---------------------------------------------------------------------------
// merged init: zero degree arrays + weight transpose to fp16
// ---------------------------------------------------------------------------
__global__ void k_init(const float* __restrict__ W1, const float* __restrict__ rW1,
                       const float* __restrict__ W2, const float* __restrict__ rW2,
                       int Nn)
{
    int i = blockIdx.x * blockDim.x + threadIdx.x;
    if (i < Nn) { g_deg_src[i] = 0; g_deg_dst[i] = 0; }
    if (i < 2 * 256 * 128) {
        int layer = i >> 15;
        int j = i & 32767;
        int n = j >> 7, k = j & 127;
        const float* src = (layer == 0) ? ((n < 128) ? W1 : rW1)
                                        : ((n < 128) ? W2 : rW2);
        g_Wt[layer][(size_t)n * 128 + k] = __float2half(src[(size_t)k * 128 + (n & 127)]);
    }
}

__global__ void k_deg(const int* __restrict__ src, const int* __restrict__ dst, int E) {
    int e = blockIdx.x * blockDim.x + threadIdx.x;
    if (e < E) {
        atomicAdd(&g_deg_src[src[e]], 1);
        atomicAdd(&g_deg_dst[dst[e]], 1);
    }
}

// fused: norms + per-chunk sum of deg_dst
__global__ void k_normchunk(int Nn) {
    __shared__ int sdata[256];
    int base = blockIdx.x * SCAN_CHUNK;
    int s = 0;
    for (int i = threadIdx.x; i < SCAN_CHUNK; i += 256) {
        int idx = base + i;
        if (idx < Nn) {
            int ds = g_deg_src[idx], dd = g_deg_dst[idx];
            g_out_norm[idx] = rsqrtf((float)max(ds, 1));
            g_in_norm[idx]  = rsqrtf((float)max(dd, 1));
            s += dd;
        }
    }
    sdata[threadIdx.x] = s;
    __syncthreads();
    for (int off = 128; off > 0; off >>= 1) {
        if (threadIdx.x < off) sdata[threadIdx.x] += sdata[threadIdx.x + off];
        __syncthreads();
    }
    if (threadIdx.x == 0) g_bsum[blockIdx.x] = sdata[0];
}

// merged scan: per-block offset + local scan -> row_ptr/cursor
__global__ void k_scan2(int Nn) {
    __shared__ int s0[SCAN_CHUNK];
    __shared__ int s1[SCAN_CHUNK];
    __shared__ int rs[256];
    int t = threadIdx.x;
    int base = blockIdx.x * SCAN_CHUNK;

    int p = 0;
    for (int i = t; i < blockIdx.x; i += 256) p += g_bsum[i];
    rs[t] = p;
    __syncthreads();
    for (int o = 128; o > 0; o >>= 1) {
        if (t < o) rs[t] += rs[t + o];
        __syncthreads();
    }
    int off = rs[0];

    for (int i = t; i < SCAN_CHUNK; i += 256) {
        int idx = base + i;
        s0[i] = (idx < Nn) ? g_deg_dst[idx] : 0;
    }
    __syncthreads();
    int* a = s0; int* b = s1;
    for (int d = 1; d < SCAN_CHUNK; d <<= 1) {
        for (int i = t; i < SCAN_CHUNK; i += 256)
            b[i] = a[i] + (i >= d ? a[i - d] : 0);
        __syncthreads();
        int* tmp = a; a = b; b = tmp;
    }
    for (int i = t; i < SCAN_CHUNK; i += 256) {
        int idx = base + i;
        if (idx < Nn) {
            int ex = off + (i > 0 ? a[i - 1] : 0);
            g_row_ptr[idx] = ex;
            g_cursor[idx]  = ex;
        }
    }
    if (blockIdx.x == gridDim.x - 1 && t == 0)
        g_row_ptr[Nn] = off + a[SCAN_CHUNK - 1];
}

__global__ void k_build(const int* __restrict__ src, const int* __restrict__ dst, int E) {
    int e = blockIdx.x * blockDim.x + threadIdx.x;
    if (e < E) {
        int p = atomicAdd(&g_cursor[dst[e]], 1);
        g_esrc[p] = src[e];
    }
}

// ---------------------------------------------------------------------------
// fused fp16 tensor-core GEMM core (one barrier, W+X smem resident)
// block 128 rows x 256 cols, 1024 thr (32 warps, 4M x 8N), warp tile 32x32
// Epilogue: cols [0,128) -> Pout fp16 * rowscale; [128,256) -> RoutH relu fp16
// ---------------------------------------------------------------------------
#define WP 136
#define GEMM_SMEM ((256 * WP + 128 * WP) * 2)   // 104448 bytes

#define MMA_F16(c, a0, a1, a2, a3, b0, b1)                                   \
    asm volatile(                                                            \
        "mma.sync.aligned.m16n8k16.row.col.f32.f16.f16.f32 "                 \
        "{%0,%1,%2,%3}, {%4,%5,%6,%7}, {%8,%9}, {%0,%1,%2,%3};"              \
        : "+f"((c)[0]), "+f"((c)[1]), "+f"((c)[2]), "+f"((c)[3])             \
        : "r"(a0), "r"(a1), "r"(a2), "r"(a3), "r"(b0), "r"(b1))

#define GEMM_MAIN_AND_EPI()                                                  \
    float acc[2][4][4];                                                      \
    _Pragma("unroll")                                                        \
    for (int mt = 0; mt < 2; mt++)                                           \
        _Pragma("unroll")                                                    \
        for (int nt = 0; nt < 4; nt++)                                       \
            _Pragma("unroll")                                                \
            for (int q = 0; q < 4; q++) acc[mt][nt][q] = 0.f;                \
    _Pragma("unroll")                                                        \
    for (int c = 0; c < 8; c++) {                                            \
        int kk = c * 16;                                                     \
        uint32_t a[2][4];                                                    \
        _Pragma("unroll")                                                    \
        for (int mt = 0; mt < 2; mt++) {                                     \
            int r = wm * 32 + mt * 16 + gq;                                  \
            a[mt][0] = *reinterpret_cast<uint32_t*>(&Xs[r * WP + kk + tg * 2]);          \
            a[mt][1] = *reinterpret_cast<uint32_t*>(&Xs[(r + 8) * WP + kk + tg * 2]);    \
            a[mt][2] = *reinterpret_cast<uint32_t*>(&Xs[r * WP + kk + 8 + tg * 2]);      \
            a[mt][3] = *reinterpret_cast<uint32_t*>(&Xs[(r + 8) * WP + kk + 8 + tg * 2]);\
        }                                                                    \
        _Pragma("unroll")                                                    \
        for (int nt = 0; nt < 4; nt++) {                                     \
            int nb = wn * 32 + nt * 8 + gq;                                  \
            uint32_t b0 = *reinterpret_cast<uint32_t*>(&Ws[nb * WP + kk + tg * 2]);      \
            uint32_t b1 = *reinterpret_cast<uint32_t*>(&Ws[nb * WP + kk + 8 + tg * 2]);  \
            _Pragma("unroll")                                                \
            for (int mt = 0; mt < 2; mt++)                                   \
                MMA_F16(acc[mt][nt], a[mt][0], a[mt][1], a[mt][2], a[mt][3], b0, b1);    \
        }                                                                    \
    }                                                                        \
    _Pragma("unroll")                                                        \
    for (int mt = 0; mt < 2; mt++) {                                         \
        int r0 = row0 + wm * 32 + mt * 16 + gq;                              \
        int r1 = r0 + 8;                                                     \
        if (wn < 4) {                                                        \
            float s0 = (r0 < M) ? rowscale[r0] : 0.f;                        \
            float s1 = (r1 < M) ? rowscale[r1] : 0.f;                        \
            _Pragma("unroll")                                                \
            for (int nt = 0; nt < 4; nt++) {                                 \
                int c = wn * 32 + nt * 8 + tg * 2;                           \
                float* a = acc[mt][nt];                                      \
                if (r0 < M)                                                  \
                    *reinterpret_cast<__half2*>(&Pout[(size_t)r0 * 128 + c]) =           \
                        __floats2half2_rn(a[0] * s0, a[1] * s0);             \
                if (r1 < M)                                                  \
                    *reinterpret_cast<__half2*>(&Pout[(size_t)r1 * 128 + c]) =           \
                        __floats2half2_rn(a[2] * s1, a[3] * s1);             \
            }                                                                \
        } else {                                                             \
            _Pragma("unroll")                                                \
            for (int nt = 0; nt < 4; nt++) {                                 \
                int c = (wn - 4) * 32 + nt * 8 + tg * 2;                     \
                float* a = acc[mt][nt];                                      \
                float b0 = resb[c], b1 = resb[c + 1];                        \
                if (r0 < M)                                                  \
                    *reinterpret_cast<__half2*>(&RoutH[(size_t)r0 * 128 + c]) =          \
                        __floats2half2_rn(fmaxf(a[0] + b0, 0.f), fmaxf(a[1] + b1, 0.f)); \
                if (r1 < M)                                                  \
                    *reinterpret_cast<__half2*>(&RoutH[(size_t)r1 * 128 + c]) =          \
                        __floats2half2_rn(fmaxf(a[2] + b0, 0.f), fmaxf(a[3] + b1, 0.f)); \
            }                                                                \
        }                                                                    \
    }

// ---- layer 1: X from fp32 global ----
__global__ __launch_bounds__(1024) void k_gemm_l1(
    const float* __restrict__ X, const __half* __restrict__ Wt,
    const float* __restrict__ resb, const float* __restrict__ rowscale,
    __half* __restrict__ Pout, __half* __restrict__ RoutH, int M)
{
    extern __shared__ __half sm[];
    __half* Ws = sm;
    __half* Xs = sm + 256 * WP;
    int tid = threadIdx.x;
    int lane = tid & 31, wid = tid >> 5;
    int wm = wid & 3, wn = wid >> 2;
    int gq = lane >> 2, tg = lane & 3;
    int row0 = blockIdx.x * 128;

#pragma unroll
    for (int i = tid; i < 4096; i += 1024) {
        int n = i >> 4, kb = (i & 15) * 8;
        *reinterpret_cast<uint4*>(&Ws[n * WP + kb]) =
            *reinterpret_cast<const uint4*>(&Wt[(size_t)n * 128 + kb]);
    }
    {
        int xr = tid >> 3, xc0 = (tid & 7) * 16;
        int gr = row0 + xr;
        bool rowok = (gr < M);
        const float4* xrow = reinterpret_cast<const float4*>(&X[(size_t)gr * 128 + xc0]);
#pragma unroll
        for (int j = 0; j < 4; j++) {
            float4 v = make_float4(0.f, 0.f, 0.f, 0.f);
            if (rowok) v = xrow[j];
            __half2 h01 = __floats2half2_rn(v.x, v.y);
            __half2 h23 = __floats2half2_rn(v.z, v.w);
            uint2 u;
            u.x = *reinterpret_cast<uint32_t*>(&h01);
            u.y = *reinterpret_cast<uint32_t*>(&h23);
            *reinterpret_cast<uint2*>(&Xs[xr * WP + xc0 + j * 4]) = u;
        }
    }
    __syncthreads();
    GEMM_MAIN_AND_EPI()
}

// ---- layer 2: X from fp16 global (H1) ----
__global__ __launch_bounds__(1024) void k_gemm_l2h(
    const __half* __restrict__ Xh, const __half* __restrict__ Wt,
    const float* __restrict__ resb, const float* __restrict__ rowscale,
    __half* __restrict__ Pout, __half* __restrict__ RoutH, int M)
{
    extern __shared__ __half sm[];
    __half* Ws = sm;
    __half* Xs = sm + 256 * WP;
    int tid = threadIdx.x;
    int lane = tid & 31, wid = tid >> 5;
    int wm = wid & 3, wn = wid >> 2;
    int gq = lane >> 2, tg = lane & 3;
    int row0 = blockIdx.x * 128;

#pragma unroll
    for (int i = tid; i < 4096; i += 1024) {
        int n = i >> 4, kb = (i & 15) * 8;
        *reinterpret_cast<uint4*>(&Ws[n * WP + kb]) =
            *reinterpret_cast<const uint4*>(&Wt[(size_t)n * 128 + kb]);
    }
    {
        int xr = tid >> 3, xc0 = (tid & 7) * 16;
        int gr = row0 + xr;
        bool rowok = (gr < M);
        const uint4* xrow = reinterpret_cast<const uint4*>(&Xh[(size_t)gr * 128 + xc0]);
#pragma unroll
        for (int j = 0; j < 2; j++) {
            uint4 v = make_uint4(0u, 0u, 0u, 0u);
            if (rowok) v = xrow[j];
            *reinterpret_cast<uint4*>(&Xs[xr * WP + xc0 + j * 8]) = v;
        }
    }
    __syncthreads();
    GEMM_MAIN_AND_EPI()
}

// ---------------------------------------------------------------------------
// aggregation: warp per node, fp16 P rows + fp16 R, 4-edge unroll, fp32 accum
// ---------------------------------------------------------------------------
__device__ __forceinline__ float4 agg_node(const __half* __restrict__ P,
                                           const __half* __restrict__ R,
                                           float4 b, int w, int lane)
{
    int e0 = g_row_ptr[w], e1 = g_row_ptr[w + 1];
    const uint2* P2 = reinterpret_cast<const uint2*>(P);
    float4 acc = make_float4(0.f, 0.f, 0.f, 0.f);
    int e = e0;
#define ACCV(v) { \
    float2 p0 = __half22float2(*reinterpret_cast<__half2*>(&(v).x)); \
    float2 p1 = __half22float2(*reinterpret_cast<__half2*>(&(v).y)); \
    acc.x += p0.x; acc.y += p0.y; acc.z += p1.x; acc.w += p1.y; }
    for (; e + 3 < e1; e += 4) {
        int u0 = g_esrc[e],     u1 = g_esrc[e + 1];
        int u2 = g_esrc[e + 2], u3 = g_esrc[e + 3];
        uint2 v0 = P2[(size_t)u0 * 32 + lane];
        uint2 v1 = P2[(size_t)u1 * 32 + lane];
        uint2 v2 = P2[(size_t)u2 * 32 + lane];
        uint2 v3 = P2[(size_t)u3 * 32 + lane];
        ACCV(v0); ACCV(v1); ACCV(v2); ACCV(v3);
    }
    for (; e < e1; e++) {
        int u = g_esrc[e];
        uint2 v = P2[(size_t)u * 32 + lane];
        ACCV(v);
    }
#undef ACCV
    float inn = g_in_norm[w];
    uint2 rv = reinterpret_cast<const uint2*>(R)[(size_t)w * 32 + lane];
    float2 r01 = __half22float2(*reinterpret_cast<__half2*>(&rv.x));
    float2 r23 = __half22float2(*reinterpret_cast<__half2*>(&rv.y));
    float4 o;
    o.x = fmaxf(fmaf(acc.x, inn, b.x), 0.f) + r01.x;
    o.y = fmaxf(fmaf(acc.y, inn, b.y), 0.f) + r01.y;
    o.z = fmaxf(fmaf(acc.z, inn, b.z), 0.f) + r23.x;
    o.w = fmaxf(fmaf(acc.w, inn, b.w), 0.f) + r23.y;
    return o;
}

__global__ void k_agg_h(const __half* __restrict__ P, const __half* __restrict__ R,
                        const float* __restrict__ bias, int Nn, __half* __restrict__ out)
{
    int w = (int)((blockIdx.x * (size_t)blockDim.x + threadIdx.x) >> 5);
    int lane = threadIdx.x & 31;
    if (w >= Nn) return;
    float4 b = reinterpret_cast<const float4*>(bias)[lane];
    float4 o = agg_node(P, R, b, w, lane);
    __half2 h01 = __floats2half2_rn(o.x, o.y);
    __half2 h23 = __floats2half2_rn(o.z, o.w);
    uint2 u;
    u.x = *reinterpret_cast<uint32_t*>(&h01);
    u.y = *reinterpret_cast<uint32_t*>(&h23);
    reinterpret_cast<uint2*>(out)[(size_t)w * 32 + lane] = u;
}

// ---------------------------------------------------------------------------
// readout: warp per graph, H in fp16; X2 row = [hsum|hmax]
// ---------------------------------------------------------------------------
__global__ void k_readout(const __half* __restrict__ H, const int* __restrict__ gid,
                          const float* __restrict__ awW, const float* __restrict__ awb,
                          float* __restrict__ X2, int Nn, int Bg)
{
    int g = (int)((blockIdx.x * (size_t)blockDim.x + threadIdx.x) >> 5);
    int lane = threadIdx.x & 31;
    if (g >= Bg) return;
    int lo = 0, hi = Nn;
    while (lo < hi) { int mid = (lo + hi) >> 1; if (gid[mid] < g) lo = mid + 1; else hi = mid; }
    int lo2 = lo, hi2 = Nn;
    while (lo2 < hi2) { int mid = (lo2 + hi2) >> 1; if (gid[mid] < g + 1) lo2 = mid + 1; else hi2 = mid; }

    float4 a = reinterpret_cast<const float4*>(awW)[lane];
    float ab = awb[0];
    float4 s  = make_float4(0.f, 0.f, 0.f, 0.f);
    float4 mx = make_float4(0.f, 0.f, 0.f, 0.f);   // h >= 0
    const uint2* H2v = reinterpret_cast<const uint2*>(H);
    for (int i = lo; i < lo2; i++) {
        uint2 hv = H2v[(size_t)i * 32 + lane];
        float2 h01 = __half22float2(*reinterpret_cast<__half2*>(&hv.x));
        float2 h23 = __half22float2(*reinterpret_cast<__half2*>(&hv.y));
        float4 h = make_float4(h01.x, h01.y, h23.x, h23.y);
        float d = h.x * a.x + h.y * a.y + h.z * a.z + h.w * a.w;
#pragma unroll
        for (int o = 16; o; o >>= 1) d += __shfl_xor_sync(0xffffffffu, d, o);
        float aw = 1.f / (1.f + expf(-(d + ab)));
        s.x += aw * h.x; s.y += aw * h.y; s.z += aw * h.z; s.w += aw * h.w;
        mx.x = fmaxf(mx.x, h.x); mx.y = fmaxf(mx.y, h.y);
        mx.z = fmaxf(mx.z, h.z); mx.w = fmaxf(mx.w, h.w);
    }
    *reinterpret_cast<float4*>(&X2[(size_t)g * 256 + lane * 4]) = s;
    *reinterpret_cast<float4*>(&X2[(size_t)g * 256 + 128 + lane * 4]) = mx;
}

// ---------------------------------------------------------------------------
// fused MLP head: 8 graphs/block, 128 threads
// ---------------------------------------------------------------------------
__global__ __launch_bounds__(128) void k_head(
    const float* __restrict__ X2,
    const float* __restrict__ orW1, const float* __restrict__ orb1,
    const float* __restrict__ org,  const float* __restrict__ orbeta,
    const float* __restrict__ orW2, const float* __restrict__ orb2,
    const float* __restrict__ scW1, const float* __restrict__ scb1,
    const float* __restrict__ scg,  const float* __restrict__ scbeta,
    const float* __restrict__ scW2, const float* __restrict__ scb2,
    float* __restrict__ out, float* __restrict__ out_sc,
    int Bg, int T1, int T2)
{
    __shared__ float gS[8][256];
    __shared__ float z1S[8][128];
    __shared__ float orlS[8][576];   // T1 <= 576
    __shared__ float z2S[8][128];
    int tid = threadIdx.x;
    int row0 = blockIdx.x * 8;

    for (int i = tid; i < 8 * 64; i += 128) {
        int r = i >> 6, c4 = (i & 63) * 4;
        int gr = row0 + r;
        float4 v = make_float4(0.f, 0.f, 0.f, 0.f);
        if (gr < Bg) v = *reinterpret_cast<const float4*>(&X2[(size_t)gr * 256 + c4]);
        *reinterpret_cast<float4*>(&gS[r][c4]) = v;
    }
    __syncthreads();

    // stage 1
    {
        int gc = tid;
        float acc[8];
#pragma unroll
        for (int r = 0; r < 8; r++) acc[r] = 0.f;
#pragma unroll 4
        for (int k0 = 0; k0 < 256; k0 += 4) {
            float w0 = orW1[(size_t)(k0 + 0) * 128 + gc];
            float w1 = orW1[(size_t)(k0 + 1) * 128 + gc];
            float w2 = orW1[(size_t)(k0 + 2) * 128 + gc];
            float w3 = orW1[(size_t)(k0 + 3) * 128 + gc];
#pragma unroll
            for (int r = 0; r < 8; r++) {
                float4 a = *reinterpret_cast<const float4*>(&gS[r][k0]);
                acc[r] = fmaf(a.x, w0, acc[r]);
                acc[r] = fmaf(a.y, w1, acc[r]);
                acc[r] = fmaf(a.z, w2, acc[r]);
                acc[r] = fmaf(a.w, w3, acc[r]);
            }
        }
        float bv = orb1[gc], gam = org[gc] * BN_INV, bet = orbeta[gc];
#pragma unroll
        for (int r = 0; r < 8; r++)
            z1S[r][gc] = fmaxf(acc[r] + bv, 0.f) * gam + bet;
    }
    __syncthreads();

    // stage 2
    for (int c0 = 0; c0 < T1; c0 += 128) {
        int gc = c0 + tid;
        if (gc < T1) {
            float acc[8];
#pragma unroll
            for (int r = 0; r < 8; r++) acc[r] = 0.f;
#pragma unroll 4
            for (int k0 = 0; k0 < 128; k0 += 4) {
                float w0 = orW2[(size_t)(k0 + 0) * T1 + gc];
                float w1 = orW2[(size_t)(k0 + 1) * T1 + gc];
                float w2 = orW2[(size_t)(k0 + 2) * T1 + gc];
                float w3 = orW2[(size_t)(k0 + 3) * T1 + gc];
#pragma unroll
                for (int r = 0; r < 8; r++) {
                    float4 a = *reinterpret_cast<const float4*>(&z1S[r][k0]);
                    acc[r] = fmaf(a.x, w0, acc[r]);
                    acc[r] = fmaf(a.y, w1, acc[r]);
                    acc[r] = fmaf(a.z, w2, acc[r]);
                    acc[r] = fmaf(a.w, w3, acc[r]);
                }
            }
            float bv = orb2[gc];
#pragma unroll
            for (int r = 0; r < 8; r++) {
                float v = acc[r] + bv;
                orlS[r][gc] = v;
                int gr = row0 + r;
                if (gr < Bg) out[(size_t)gr * T1 + gc] = v;
            }
        }
    }
    __syncthreads();

    // stage 3
    {
        int gc = tid;
        float acc[8];
#pragma unroll
        for (int r = 0; r < 8; r++) acc[r] = 0.f;
#pragma unroll 4
        for (int k0 = 0; k0 < 256; k0 += 4) {
            float w0 = scW1[(size_t)(k0 + 0) * 128 + gc];
            float w1 = scW1[(size_t)(k0 + 1) * 128 + gc];
            float w2 = scW1[(size_t)(k0 + 2) * 128 + gc];
            float w3 = scW1[(size_t)(k0 + 3) * 128 + gc];
#pragma unroll
            for (int r = 0; r < 8; r++) {
                float4 a = *reinterpret_cast<const float4*>(&gS[r][k0]);
                acc[r] = fmaf(a.x, w0, acc[r]);
                acc[r] = fmaf(a.y, w1, acc[r]);
                acc[r] = fmaf(a.z, w2, acc[r]);
                acc[r] = fmaf(a.w, w3, acc[r]);
            }
        }
        const float* scW1b = scW1 + (size_t)256 * 128;
#pragma unroll 4
        for (int k0 = 0; k0 < T1; k0 += 2) {
            float w0 = scW1b[(size_t)(k0 + 0) * 128 + gc];
            float w1 = scW1b[(size_t)(k0 + 1) * 128 + gc];
#pragma unroll
            for (int r = 0; r < 8; r++) {
                float2 a = *reinterpret_cast<const float2*>(&orlS[r][k0]);
                acc[r] = fmaf(a.x, w0, acc[r]);
                acc[r] = fmaf(a.y, w1, acc[r]);
            }
        }
        float bv = scb1[gc], gam = scg[gc] * BN_INV, bet = scbeta[gc];
#pragma unroll
        for (int r = 0; r < 8; r++)
            z2S[r][gc] = fmaxf(acc[r] + bv, 0.f) * gam + bet;
    }
    __syncthreads();

    // stage 4
    for (int c0 = 0; c0 < T2; c0 += 128) {
        int gc = c0 + tid;
        if (gc < T2) {
            float acc[8];
#pragma unroll
            for (int r = 0; r < 8; r++) acc[r] = 0.f;
#pragma unroll 4
            for (int k0 = 0; k0 < 128; k0 += 4) {
                float w0 = scW2[(size_t)(k0 + 0) * T2 + gc];
                float w1 = scW2[(size_t)(k0 + 1) * T2 + gc];
                float w2 = scW2[(size_t)(k0 + 2) * T2 + gc];
                float w3 = scW2[(size_t)(k0 + 3) * T2 + gc];
#pragma unroll
                for (int r = 0; r < 8; r++) {
                    float4 a = *reinterpret_cast<const float4*>(&z2S[r][k0]);
                    acc[r] = fmaf(a.x, w0, acc[r]);
                    acc[r] = fmaf(a.y, w1, acc[r]);
                    acc[r] = fmaf(a.z, w2, acc[r]);
                    acc[r] = fmaf(a.w, w3, acc[r]);
                }
            }
            float bv = scb2[gc];
#pragma unroll
            for (int r = 0; r < 8; r++) {
                int gr = row0 + r;
                if (gr < Bg) out_sc[(size_t)gr * T2 + gc] = acc[r] + bv;
            }
        }
    }
}

// ---------------------------------------------------------------------------
// host (pure stream-0; no streams/events — graph-capture safe)
// ---------------------------------------------------------------------------
extern "C" void kernel_launch(void* const* d_in, const int* in_sizes, int n_in,
                              void* d_out, int out_size)
{
    const float* feats  = (const float*)d_in[0];
    const int*   src    = (const int*)  d_in[1];
    const int*   dst    = (const int*)  d_in[2];
    const int*   gid    = (const int*)  d_in[3];
    const float* W1     = (const float*)d_in[4];
    const float* b1     = (const float*)d_in[5];
    const float* resW1  = (const float*)d_in[6];
    const float* resb1  = (const float*)d_in[7];
    const float* W2     = (const float*)d_in[8];
    const float* b2     = (const float*)d_in[9];
    const float* resW2  = (const float*)d_in[10];
    const float* resb2  = (const float*)d_in[11];
    const float* awW    = (const float*)d_in[12];
    const float* awb    = (const float*)d_in[13];
    const float* orW1   = (const float*)d_in[14];
    const float* orb1   = (const float*)d_in[15];
    const float* org    = (const float*)d_in[16];
    const float* orbeta = (const float*)d_in[17];
    const float* orW2   = (const float*)d_in[18];
    const float* orb2   = (const float*)d_in[19];
    const float* scW1   = (const float*)d_in[20];
    const float* scb1   = (const float*)d_in[21];
    const float* scg    = (const float*)d_in[22];
    const float* scbeta = (const float*)d_in[23];
    const float* scW2   = (const float*)d_in[24];
    const float* scb2   = (const float*)d_in[25];

    int N  = in_sizes[0] / HD;
    int E  = in_sizes[1];
    int T1 = in_sizes[19];
    int T2 = in_sizes[25];
    int B  = out_size / (T1 + T2);

    float* out    = (float*)d_out;
    float* out_sc = out + (size_t)B * T1;

    void *pPh, *pRh, *pHh, *pX2, *pON, *pWt;
    cudaGetSymbolAddress(&pPh, g_Ph);
    cudaGetSymbolAddress(&pRh, g_Rh);
    cudaGetSymbolAddress(&pHh, g_Hh);
    cudaGetSymbolAddress(&pX2, g_X2);
    cudaGetSymbolAddress(&pON, g_out_norm);
    cudaGetSymbolAddress(&pWt, g_Wt);
    __half* Ph = (__half*)pPh;
    __half* Rh = (__half*)pRh;
    __half* Hh = (__half*)pHh;
    float*  X2 = (float*)pX2;
    float*  ONm = (float*)pON;
    __half* Wt0 = (__half*)pWt;
    __half* Wt1 = Wt0 + (size_t)256 * 128;

    cudaFuncSetAttribute(k_gemm_l1,  cudaFuncAttributeMaxDynamicSharedMemorySize, GEMM_SMEM);
    cudaFuncSetAttribute(k_gemm_l2h, cudaFuncAttributeMaxDynamicSharedMemorySize, GEMM_SMEM);

    int eb = (E + 255) / 256;
    int nb = (N + SCAN_CHUNK - 1) / SCAN_CHUNK;
    int gb = (N + 127) / 128;
    int wb = (N + 7) / 8;
    int icnt = (N > 2 * 256 * 128) ? N : (2 * 256 * 128);
    int ib = (icnt + 255) / 256;

    // launches: 1 init, 2 deg, 3 normchunk, 4 scan2, 5 build,
    //           6 gemm_l1 <- ncu skip-5 profile slot
    k_init<<<ib, 256>>>(W1, resW1, W2, resW2, N);
    k_deg<<<eb, 256>>>(src, dst, E);
    k_normchunk<<<nb, 256>>>(N);
    k_scan2<<<nb, 256>>>(N);
    k_build<<<eb, 256>>>(src, dst, E);

    k_gemm_l1<<<gb, 1024, GEMM_SMEM>>>(feats, Wt0, resb1, ONm, Ph, Rh, N);
    k_agg_h<<<wb, 256>>>(Ph, Rh, b1, N, Hh);                 // H1 fp16

    k_gemm_l2h<<<gb, 1024, GEMM_SMEM>>>(Hh, Wt1, resb2, ONm, Ph, Rh, N);
    k_agg_h<<<wb, 256>>>(Ph, Rh, b2, N, Hh);                 // H2 fp16

    k_readout<<<(B + 7) / 8, 256>>>(Hh, gid, awW, awb, X2, N, B);

    k_head<<<(B + 7) / 8, 128>>>(X2, orW1, orb1, org, orbeta, orW2, orb2,
                                 scW1, scb1, scg, scbeta, scW2, scb2,
                                 out, out_sc, B, T1, T2);
}